// round 10
// baseline (speedup 1.0000x reference)
#include <cuda_runtime.h>
#include <cuda_bf16.h>
#include <cuda_fp16.h>
#include <math.h>

#define NATM 200000
#define NBLK 50000
#define NE   450000
#define NG   64
#define HID  128
#define RAD  64
#define EDGEF 256
#define NLAY 3
#define TABN 8192          // nearest-neighbor table, spacing 1/1024 over [0,8)
#define TABSCALE 1024.0f

// ---- scratch layout (single __device__ buffer, floats) ----
static const size_t OFF_H     = 0;          // [NBLK*128]
static const size_t OFF_ZC    = 6400000;    // [NBLK*4] z0,z1,z2,cnt
static const size_t OFF_A     = 6600000;    // [NBLK*256]
static const size_t OFF_B     = 19400000;   // [NBLK*256]
static const size_t OFF_AGG   = 32200000;   // [NBLK*256]
static const size_t OFF_TAB   = 45000000;   // [3*8192*256] halfs (3.15M floats)
static const size_t OFF_WC    = 51291456;   // [3*64*256]
static const size_t OFF_GACC  = 51340608;   // [64*128]
static const size_t OFF_START = 51348800;   // int[NBLK+1]
static const size_t OFF_CNT   = 51398816;   // int[NBLK] (becomes end offsets)
static const size_t OFF_TOPS  = 51448832;   // int[128]
static const size_t OFF_SSIT  = 51448960;   // int2[NE] (src, table row)
static const size_t SCR_TOTAL = 52349056;

__device__ __align__(16) float g_scratch[SCR_TOTAL];

#define NTOPS 98   // ceil(NBLK/512)

__device__ __forceinline__ float silu_f(float x) {
    return x / (1.0f + __expf(-x));
}

__device__ __forceinline__ unsigned cvt_tf32(float f) {
    unsigned u;
    asm("cvt.rna.tf32.f32 %0, %1;" : "=r"(u) : "f"(f));
    return u;
}

__device__ __forceinline__ void mma_tf32(float* c, const unsigned* a,
                                         const unsigned* b) {
    asm volatile(
        "mma.sync.aligned.m16n8k8.row.col.f32.tf32.tf32.f32 "
        "{%0,%1,%2,%3}, {%4,%5,%6,%7}, {%8,%9}, {%0,%1,%2,%3};"
        : "+f"(c[0]), "+f"(c[1]), "+f"(c[2]), "+f"(c[3])
        : "r"(a[0]), "r"(a[1]), "r"(a[2]), "r"(a[3]), "r"(b[0]), "r"(b[1]));
}

__device__ __forceinline__ void red4(float* p, float4 v) {
    asm volatile("red.global.add.v4.f32 [%0], {%1,%2,%3,%4};"
                 :: "l"(p), "f"(v.x), "f"(v.y), "f"(v.z), "f"(v.w)
                 : "memory");
}

// ---------------------------------------------------------------------------
__global__ void k_zero4(float* __restrict__ p, int n4) {
    float4 z = make_float4(0.f, 0.f, 0.f, 0.f);
    for (int i = blockIdx.x * blockDim.x + threadIdx.x; i < n4;
         i += gridDim.x * blockDim.x) {
        ((float4*)p)[i] = z;
    }
}

// ---------------------------------------------------------------------------
// segment boundaries of sorted block_id
// ---------------------------------------------------------------------------
__global__ void k_bounds(const int* __restrict__ bid, int* __restrict__ start) {
    int a = blockIdx.x * blockDim.x + threadIdx.x;
    if (a > NATM) return;
    if (a == 0) {
        int c = bid[0];
        for (int b = 0; b <= c; b++) start[b] = 0;
    } else if (a == NATM) {
        int p = bid[NATM - 1];
        for (int b = p + 1; b <= NBLK; b++) start[b] = NATM;
    } else {
        int p = bid[a - 1], c = bid[a];
        for (int b = p + 1; b <= c; b++) start[b] = a;
    }
}

// ---------------------------------------------------------------------------
// segment-mean pooling: one warp per block
// ---------------------------------------------------------------------------
__global__ void k_pool(const float* __restrict__ H, const float* __restrict__ Z,
                       const int* __restrict__ start, float* __restrict__ h,
                       float* __restrict__ zc, float* __restrict__ outHb) {
    int gt = blockIdx.x * blockDim.x + threadIdx.x;
    int b = gt >> 5;
    int lane = gt & 31;
    if (b >= NBLK) return;
    int lo = start[b], hi = start[b + 1];
    float4 hs = make_float4(0.f, 0.f, 0.f, 0.f);
    for (int a = lo; a < hi; a++) {
        float4 v = *(const float4*)&H[(size_t)a * HID + lane * 4];
        hs.x += v.x; hs.y += v.y; hs.z += v.z; hs.w += v.w;
    }
    float zx = 0.f, zy = 0.f, zz = 0.f;
    for (int a = lo + lane; a < hi; a += 32) {
        zx += Z[a * 3 + 0]; zy += Z[a * 3 + 1]; zz += Z[a * 3 + 2];
    }
#pragma unroll
    for (int o = 16; o > 0; o >>= 1) {
        zx += __shfl_xor_sync(0xffffffffu, zx, o);
        zy += __shfl_xor_sync(0xffffffffu, zy, o);
        zz += __shfl_xor_sync(0xffffffffu, zz, o);
    }
    float cnt = (float)(hi - lo);
    float inv = 1.0f / fmaxf(cnt, 1.0f);
    hs.x *= inv; hs.y *= inv; hs.z *= inv; hs.w *= inv;
    *(float4*)&h[(size_t)b * HID + lane * 4] = hs;
    *(float4*)&outHb[(size_t)b * HID + lane * 4] = hs;
    if (lane == 0) {
        zc[b * 4 + 0] = zx * inv;
        zc[b * 4 + 1] = zy * inv;
        zc[b * 4 + 2] = zz * inv;
        zc[b * 4 + 3] = cnt;
    }
}

// ---------------------------------------------------------------------------
// counting sort of edges by dst
// ---------------------------------------------------------------------------
__global__ void k_hist(const int* __restrict__ edges, int* __restrict__ cnt) {
    int e = blockIdx.x * blockDim.x + threadIdx.x;
    if (e < NE) atomicAdd(&cnt[edges[NE + e]], 1);
}

__global__ void k_scan1(const int* __restrict__ cnt, int* __restrict__ offs,
                        int* __restrict__ tops) {
    __shared__ int sh[512];
    int i = blockIdx.x * 512 + threadIdx.x;
    int v = (i < NBLK) ? cnt[i] : 0;
    sh[threadIdx.x] = v;
    __syncthreads();
#pragma unroll
    for (int off = 1; off < 512; off <<= 1) {
        int t = 0;
        if (threadIdx.x >= off) t = sh[threadIdx.x - off];
        __syncthreads();
        if (threadIdx.x >= off) sh[threadIdx.x] += t;
        __syncthreads();
    }
    if (i < NBLK) offs[i] = sh[threadIdx.x] - v;
    if (threadIdx.x == 511) tops[blockIdx.x] = sh[511];
}

__global__ void k_scan2(int* __restrict__ tops) {
    __shared__ int sh[128];
    int v = (threadIdx.x < NTOPS) ? tops[threadIdx.x] : 0;
    sh[threadIdx.x] = v;
    __syncthreads();
#pragma unroll
    for (int off = 1; off < 128; off <<= 1) {
        int t = 0;
        if (threadIdx.x >= off) t = sh[threadIdx.x - off];
        __syncthreads();
        if (threadIdx.x >= off) sh[threadIdx.x] += t;
        __syncthreads();
    }
    if (threadIdx.x < NTOPS) tops[threadIdx.x] = sh[threadIdx.x] - v;
}

__global__ void k_scan3(int* __restrict__ offs, const int* __restrict__ tops) {
    int i = blockIdx.x * 512 + threadIdx.x;
    if (i < NBLK) offs[i] += tops[blockIdx.x];
}

// scatter: sorted position gets (src, nearest table row index)
__global__ void k_scat(const int* __restrict__ edges, int* __restrict__ offs,
                       const float* __restrict__ zc, int2* __restrict__ ssit) {
    int e = blockIdx.x * blockDim.x + threadIdx.x;
    if (e >= NE) return;
    int s = edges[e];
    int d = edges[NE + e];
    int pos = atomicAdd(&offs[d], 1);
    float dx = zc[s * 4 + 0] - zc[d * 4 + 0];
    float dy = zc[s * 4 + 1] - zc[d * 4 + 1];
    float dz = zc[s * 4 + 2] - zc[d * 4 + 2];
    float dd = sqrtf(dx * dx + dy * dy + dz * dz + 1e-12f);
    int it = (int)(dd * TABSCALE + 0.5f);
    if (it > TABN - 1) it = TABN - 1;
    ssit[pos] = make_int2(s, it);
}
// after k_scat, offs[d] holds the END offset of dst-segment d.

// ---------------------------------------------------------------------------
// build fp16 lookup table T[l][g][j] = rbf(g/1024) @ Wc[l]
// grid (TABN/8, 3), 256 threads; 8 grid points share each W read.
// ---------------------------------------------------------------------------
__global__ void k_table(const float* __restrict__ Wc, __half* __restrict__ T) {
    __shared__ float rb[8][64];
    int g0 = blockIdx.x * 8, l = blockIdx.y;
    int tid = threadIdx.x;
    for (int i = tid; i < 8 * 64; i += 256) {
        int gi = i >> 6;
        int k = i & 63;
        float dd = (float)(g0 + gi) * (1.0f / TABSCALE)
                 - (6.0f / 63.0f) * (float)k;
        rb[gi][k] = __expf(-10.0f * dd * dd);
    }
    __syncthreads();
    const float* W = Wc + (size_t)l * 64 * 256;
    float acc[8];
#pragma unroll
    for (int gi = 0; gi < 8; gi++) acc[gi] = 0.f;
#pragma unroll 8
    for (int k = 0; k < 64; k++) {
        float w = W[k * 256 + tid];
#pragma unroll
        for (int gi = 0; gi < 8; gi++) acc[gi] += rb[gi][k] * w;
    }
    __half* out = T + ((size_t)l * TABN + g0) * 256 + tid;
#pragma unroll
    for (int gi = 0; gi < 8; gi++) out[gi * 256] = __float2half(acc[gi]);
}

// ---------------------------------------------------------------------------
// tf32 tensor GEMM, double-buffered: C[M,N] = A[M,K] @ B[K,N]
// BM=128 BN=64 BK=32, 256 threads. block.x >= ntiles0 -> (B1,C1).
// epi==1: C += silu(acc). Requires K%32==0, N%64==0.
// ---------------------------------------------------------------------------
__global__ void __launch_bounds__(256)
k_gemm(const float* __restrict__ A, const float* __restrict__ B0,
       const float* __restrict__ B1, float* __restrict__ C0,
       float* __restrict__ C1, int M, int N, int K, int epi, int ntiles0) {
    __shared__ unsigned As[128 * 36];
    __shared__ unsigned Bs[32 * 68];
    int tid = threadIdx.x;
    int warp = tid >> 5, lane = tid & 31;
    int gid = lane >> 2, tig = lane & 3;
    int wm = (warp & 3) * 32, wn = (warp >> 2) * 32;
    int rowBase = blockIdx.y * 128;
    int bx = blockIdx.x;
    const float* B = B0;
    float* C = C0;
    if (bx >= ntiles0) { B = B1; C = C1; bx -= ntiles0; }
    int colBase = bx * 64;

    int ar = tid >> 3, ac = (tid & 7) * 4;
    int br = tid >> 4, bc = (tid & 15) * 4;

    float4 av[4], bv[2];
#pragma unroll
    for (int i = 0; i < 4; i++) {
        int r = rowBase + ar + i * 32;
        av[i] = (r < M) ? *(const float4*)&A[(size_t)r * K + ac]
                        : make_float4(0.f, 0.f, 0.f, 0.f);
    }
#pragma unroll
    for (int i = 0; i < 2; i++)
        bv[i] = *(const float4*)&B[(size_t)(br + i * 16) * N + colBase + bc];

    float acc[2][4][4];
#pragma unroll
    for (int mt = 0; mt < 2; mt++)
#pragma unroll
        for (int nn = 0; nn < 4; nn++)
#pragma unroll
            for (int q = 0; q < 4; q++) acc[mt][nn][q] = 0.f;

    for (int k0 = 0; k0 < K; k0 += 32) {
#pragma unroll
        for (int i = 0; i < 4; i++) {
            uint4 u;
            u.x = cvt_tf32(av[i].x); u.y = cvt_tf32(av[i].y);
            u.z = cvt_tf32(av[i].z); u.w = cvt_tf32(av[i].w);
            *(uint4*)&As[(ar + i * 32) * 36 + ac] = u;
        }
#pragma unroll
        for (int i = 0; i < 2; i++) {
            uint4 u;
            u.x = cvt_tf32(bv[i].x); u.y = cvt_tf32(bv[i].y);
            u.z = cvt_tf32(bv[i].z); u.w = cvt_tf32(bv[i].w);
            *(uint4*)&Bs[(br + i * 16) * 68 + bc] = u;
        }
        __syncthreads();
        if (k0 + 32 < K) {
#pragma unroll
            for (int i = 0; i < 4; i++) {
                int r = rowBase + ar + i * 32;
                av[i] = (r < M)
                    ? *(const float4*)&A[(size_t)r * K + k0 + 32 + ac]
                    : make_float4(0.f, 0.f, 0.f, 0.f);
            }
#pragma unroll
            for (int i = 0; i < 2; i++)
                bv[i] = *(const float4*)
                    &B[(size_t)(k0 + 32 + br + i * 16) * N + colBase + bc];
        }
#pragma unroll
        for (int kk = 0; kk < 4; kk++) {
            unsigned a[2][4], b[4][2];
#pragma unroll
            for (int mt = 0; mt < 2; mt++) {
                int r = wm + mt * 16 + gid;
                a[mt][0] = As[r * 36 + kk * 8 + tig];
                a[mt][1] = As[(r + 8) * 36 + kk * 8 + tig];
                a[mt][2] = As[r * 36 + kk * 8 + tig + 4];
                a[mt][3] = As[(r + 8) * 36 + kk * 8 + tig + 4];
            }
#pragma unroll
            for (int nn = 0; nn < 4; nn++) {
                b[nn][0] = Bs[(kk * 8 + tig) * 68 + wn + nn * 8 + gid];
                b[nn][1] = Bs[(kk * 8 + tig + 4) * 68 + wn + nn * 8 + gid];
            }
#pragma unroll
            for (int mt = 0; mt < 2; mt++)
#pragma unroll
                for (int nn = 0; nn < 4; nn++)
                    mma_tf32(acc[mt][nn], a[mt], b[nn]);
        }
        __syncthreads();
    }

#pragma unroll
    for (int mt = 0; mt < 2; mt++) {
#pragma unroll
        for (int nn = 0; nn < 4; nn++) {
            int r0 = rowBase + wm + mt * 16 + gid;
            int r1 = r0 + 8;
            int c = colBase + wn + nn * 8 + 2 * tig;
            if (r0 < M) {
                size_t idx = (size_t)r0 * N + c;
                if (epi == 1) {
                    C[idx]     += silu_f(acc[mt][nn][0]);
                    C[idx + 1] += silu_f(acc[mt][nn][1]);
                } else {
                    C[idx]     = acc[mt][nn][0];
                    C[idx + 1] = acc[mt][nn][1];
                }
            }
            if (r1 < M) {
                size_t idx = (size_t)r1 * N + c;
                if (epi == 1) {
                    C[idx]     += silu_f(acc[mt][nn][2]);
                    C[idx + 1] += silu_f(acc[mt][nn][3]);
                } else {
                    C[idx]     = acc[mt][nn][2];
                    C[idx + 1] = acc[mt][nn][3];
                }
            }
        }
    }
}

// ---------------------------------------------------------------------------
// edge+aggregate kernel: TWO warps per dst block (128 cols each).
// agg[d] = sum_{e in seg(d)} silu(A[src_e] + B[d] + T[row_e])   (T in fp16)
// ---------------------------------------------------------------------------
__global__ void __launch_bounds__(256)
k_edge_lut(const int2* __restrict__ ssit, const int* __restrict__ eend,
           const __half* __restrict__ Tl, const float* __restrict__ Ag,
           const float* __restrict__ Bg, float* __restrict__ agg) {
    int gw = (blockIdx.x * blockDim.x + threadIdx.x) >> 5;
    int d = gw >> 1;
    int hh = gw & 1;
    int lane = threadIdx.x & 31;
    if (d >= NBLK) return;
    int lo = (d > 0) ? eend[d - 1] : 0;
    int hi = eend[d];
    int c = hh * 128 + lane * 4;

    float4 acc = make_float4(0.f, 0.f, 0.f, 0.f);

    if (lo < hi) {
        float4 b = *(const float4*)&Bg[(size_t)d * 256 + c];
        for (int e = lo; e < hi; e++) {
            int2 se = ssit[e];
            float4 a = *(const float4*)&Ag[((size_t)se.x << 8) + c];
            uint2 raw = *(const uint2*)&Tl[((size_t)se.y << 8) + c];
            float2 f0 = __half22float2(*(__half2*)&raw.x);
            float2 f1 = __half22float2(*(__half2*)&raw.y);
            acc.x += silu_f(a.x + b.x + f0.x);
            acc.y += silu_f(a.y + b.y + f0.y);
            acc.z += silu_f(a.z + b.z + f1.x);
            acc.w += silu_f(a.w + b.w + f1.y);
        }
    }
    *(float4*)&agg[(size_t)d * 256 + c] = acc;
}

// ---------------------------------------------------------------------------
__global__ void k_rownorm_scatter(const float* __restrict__ tmp,
                                  const int* __restrict__ batch_id,
                                  float* __restrict__ out_block,
                                  float* __restrict__ gacc) {
    int gt = blockIdx.x * blockDim.x + threadIdx.x;
    int r = gt >> 5;
    int lane = gt & 31;
    if (r >= NBLK) return;
    float4 v = *(const float4*)&tmp[(size_t)r * HID + lane * 4];
    float ss = v.x * v.x + v.y * v.y + v.z * v.z + v.w * v.w;
#pragma unroll
    for (int o = 16; o > 0; o >>= 1) ss += __shfl_xor_sync(0xffffffffu, ss, o);
    float inv = 1.0f / fmaxf(sqrtf(ss), 1e-12f);
    int g = batch_id[r];
    float4 nv = make_float4(v.x * inv, v.y * inv, v.z * inv, v.w * inv);
    *(float4*)&out_block[(size_t)r * HID + lane * 4] = nv;
    red4(&gacc[g * HID + lane * 4], nv);
}

__global__ void k_graphnorm(const float* __restrict__ gacc,
                            float* __restrict__ out_graph) {
    int gt = blockIdx.x * blockDim.x + threadIdx.x;
    int r = gt >> 5;
    int lane = gt & 31;
    if (r >= NG) return;
    float4 v = *(const float4*)&gacc[r * HID + lane * 4];
    float ss = v.x * v.x + v.y * v.y + v.z * v.z + v.w * v.w;
#pragma unroll
    for (int o = 16; o > 0; o >>= 1) ss += __shfl_xor_sync(0xffffffffu, ss, o);
    float inv = 1.0f / fmaxf(sqrtf(ss), 1e-12f);
    float4 nv = make_float4(v.x * inv, v.y * inv, v.z * inv, v.w * inv);
    *(float4*)&out_graph[r * HID + lane * 4] = nv;
}

// ---------------------------------------------------------------------------
extern "C" void kernel_launch(void* const* d_in, const int* in_sizes, int n_in,
                              void* d_out, int out_size) {
    const float* H      = (const float*)d_in[0];
    const float* Z      = (const float*)d_in[1];
    const float* W_rbf  = (const float*)d_in[2];
    const float* Wm1    = (const float*)d_in[3];
    const float* Wm2    = (const float*)d_in[4];
    const float* We     = (const float*)d_in[5];
    const float* Wupd   = (const float*)d_in[6];
    const float* W_out  = (const float*)d_in[7];
    const int*   block_id = (const int*)d_in[8];
    const int*   batch_id = (const int*)d_in[9];
    const int*   edges    = (const int*)d_in[10];

    float* out = (float*)d_out;
    float* out_Hb    = out;
    float* out_block = out + (size_t)NBLK * HID;
    float* out_graph = out + 2 * (size_t)NBLK * HID;

    void* scrv = nullptr;
    cudaGetSymbolAddress(&scrv, g_scratch);
    float* scr  = (float*)scrv;
    float* s_h    = scr + OFF_H;
    float* s_zc   = scr + OFF_ZC;
    float* s_A    = scr + OFF_A;
    float* s_B    = scr + OFF_B;
    float* s_agg  = scr + OFF_AGG;
    __half* s_tab = (__half*)(scr + OFF_TAB);
    float* s_Wc   = scr + OFF_WC;
    float* s_gacc = scr + OFF_GACC;
    int*   s_start = (int*)(scr + OFF_START);
    int*   s_cnt   = (int*)(scr + OFF_CNT);
    int*   s_tops  = (int*)(scr + OFF_TOPS);
    int2*  s_ssit  = (int2*)(scr + OFF_SSIT);

    dim3 gridAB(8, (NBLK + 127) / 128);
    dim3 gridUpd(2, (NBLK + 127) / 128);

    // --- order: bounds(0), pool(1), Wc0(2), AB GEMM(3 = ncu slot), Wc1, Wc2
    k_bounds<<<(NATM + 256) / 256, 256>>>(block_id, s_start);
    k_pool<<<(NBLK * 32 + 255) / 256, 256>>>(H, Z, s_start, s_h, s_zc, out_Hb);
    k_gemm<<<dim3(4, 1), 256>>>(W_rbf, We, nullptr, s_Wc, nullptr,
                                64, 256, 256, 0, 4);
    // layer-0 A/B GEMM (4th launch — profiled)
    k_gemm<<<gridAB, 256>>>(s_h, Wm1, Wm2, s_A, s_B, NBLK, EDGEF, HID, 0, 4);
    for (int l = 1; l < NLAY; l++) {
        k_gemm<<<dim3(4, 1), 256>>>(W_rbf, We + (size_t)l * 256 * 256, nullptr,
                                    s_Wc + (size_t)l * 64 * 256, nullptr,
                                    64, 256, 256, 0, 4);
    }

    // table + edge sort + misc (all complete before edge kernel 0)
    k_table<<<dim3(TABN / 8, NLAY), 256>>>(s_Wc, s_tab);
    k_zero4<<<32, 256>>>((float*)s_cnt, 50016 / 4);
    k_hist<<<(NE + 255) / 256, 256>>>(edges, s_cnt);
    k_scan1<<<NTOPS, 512>>>(s_cnt, s_cnt, s_tops);
    k_scan2<<<1, 128>>>(s_tops);
    k_scan3<<<NTOPS, 512>>>(s_cnt, s_tops);
    k_scat<<<(NE + 255) / 256, 256>>>(edges, s_cnt, s_zc, s_ssit);
    k_zero4<<<8, 256>>>(s_gacc, (NG * HID) / 4);

    for (int l = 0; l < NLAY; l++) {
        if (l > 0) {
            k_gemm<<<gridAB, 256>>>(s_h, Wm1 + (size_t)l * HID * EDGEF,
                                    Wm2 + (size_t)l * HID * EDGEF, s_A, s_B,
                                    NBLK, EDGEF, HID, 0, 4);
        }
        // fused edge messages + per-dst aggregation (2 warps per dst)
        k_edge_lut<<<(NBLK * 64 + 255) / 256, 256>>>(
            s_ssit, s_cnt, s_tab + (size_t)l * TABN * 256, s_A, s_B, s_agg);
        // h = h + silu(agg @ Wupd[l])
        k_gemm<<<gridUpd, 256>>>(s_agg, Wupd + (size_t)l * EDGEF * HID, nullptr,
                                 s_h, nullptr, NBLK, HID, EDGEF, 1, 2);
    }

    // block_repr = l2norm(h @ W_out)
    k_gemm<<<gridUpd, 256>>>(s_h, W_out, nullptr, s_A, nullptr,
                             NBLK, HID, HID, 0, 2);
    k_rownorm_scatter<<<(NBLK * 32 + 255) / 256, 256>>>(s_A, batch_id,
                                                        out_block, s_gacc);
    k_graphnorm<<<(NG * 32 + 255) / 256, 256>>>(s_gacc, out_graph);
}

// round 11
// speedup vs baseline: 1.0330x; 1.0330x over previous
#include <cuda_runtime.h>
#include <cuda_bf16.h>
#include <cuda_fp16.h>
#include <math.h>

#define NATM 200000
#define NBLK 50000
#define NE   450000
#define NG   64
#define HID  128
#define RAD  64
#define EDGEF 256
#define NLAY 3
#define TABN 8192          // nearest-neighbor table, spacing 1/1024 over [0,8)
#define TABSCALE 1024.0f

// ---- scratch layout (single __device__ buffer, floats) ----
static const size_t OFF_H     = 0;          // [NBLK*128]
static const size_t OFF_ZC    = 6400000;    // [NBLK*4] z0,z1,z2,cnt
static const size_t OFF_A     = 6600000;    // [NBLK*256]
static const size_t OFF_B     = 19400000;   // [NBLK*256]
static const size_t OFF_AGG   = 32200000;   // [NBLK*256]
static const size_t OFF_TAB   = 45000000;   // [3*8192*256] halfs (3.15M floats)
static const size_t OFF_WC    = 51291456;   // [3*64*256]
static const size_t OFF_GACC  = 51340608;   // [64*128]
static const size_t OFF_START = 51348800;   // int[NBLK+1]
static const size_t OFF_CNT   = 51398816;   // int[NBLK] (becomes end offsets)
static const size_t OFF_TOPS  = 51448832;   // int[128]
static const size_t OFF_SSIT  = 51448960;   // int2[NE] (src, table row)
static const size_t OFF_WTF   = 52349056;   // tf32 weights [507904]
static const size_t SCR_TOTAL = 52856960;

// tf32 weight sub-offsets (relative to OFF_WTF)
#define WTF_WE(l)   ((size_t)(l) * 65536)
#define WTF_WM1(l)  (196608 + (size_t)(l) * 32768)
#define WTF_WM2(l)  (294912 + (size_t)(l) * 32768)
#define WTF_WUPD(l) (393216 + (size_t)(l) * 32768)
#define WTF_WOUT    (491520)

__device__ __align__(16) float g_scratch[SCR_TOTAL];

#define NTOPS 98   // ceil(NBLK/512)

__device__ __forceinline__ float silu_f(float x) {
    return x / (1.0f + __expf(-x));
}

__device__ __forceinline__ unsigned cvt_tf32(float f) {
    unsigned u;
    asm("cvt.rna.tf32.f32 %0, %1;" : "=r"(u) : "f"(f));
    return u;
}

__device__ __forceinline__ void mma_tf32(float* c, const unsigned* a,
                                         const unsigned* b) {
    asm volatile(
        "mma.sync.aligned.m16n8k8.row.col.f32.tf32.tf32.f32 "
        "{%0,%1,%2,%3}, {%4,%5,%6,%7}, {%8,%9}, {%0,%1,%2,%3};"
        : "+f"(c[0]), "+f"(c[1]), "+f"(c[2]), "+f"(c[3])
        : "r"(a[0]), "r"(a[1]), "r"(a[2]), "r"(a[3]), "r"(b[0]), "r"(b[1]));
}

__device__ __forceinline__ void red4(float* p, float4 v) {
    asm volatile("red.global.add.v4.f32 [%0], {%1,%2,%3,%4};"
                 :: "l"(p), "f"(v.x), "f"(v.y), "f"(v.z), "f"(v.w)
                 : "memory");
}

// ---------------------------------------------------------------------------
__global__ void k_zero4(float* __restrict__ p, int n4) {
    float4 z = make_float4(0.f, 0.f, 0.f, 0.f);
    for (int i = blockIdx.x * blockDim.x + threadIdx.x; i < n4;
         i += gridDim.x * blockDim.x) {
        ((float4*)p)[i] = z;
    }
}

// convert two fp32 weight tensors to tf32 bit patterns (independent sizes)
__global__ void k_cvt2(const float* __restrict__ s0, const float* __restrict__ s1,
                       unsigned* __restrict__ d0, unsigned* __restrict__ d1,
                       int n0, int n1) {
    int i = blockIdx.x * blockDim.x + threadIdx.x;
    if (i < n0) d0[i] = cvt_tf32(s0[i]);
    if (i < n1) d1[i] = cvt_tf32(s1[i]);
}

// ---------------------------------------------------------------------------
// segment boundaries of sorted block_id
// ---------------------------------------------------------------------------
__global__ void k_bounds(const int* __restrict__ bid, int* __restrict__ start) {
    int a = blockIdx.x * blockDim.x + threadIdx.x;
    if (a > NATM) return;
    if (a == 0) {
        int c = bid[0];
        for (int b = 0; b <= c; b++) start[b] = 0;
    } else if (a == NATM) {
        int p = bid[NATM - 1];
        for (int b = p + 1; b <= NBLK; b++) start[b] = NATM;
    } else {
        int p = bid[a - 1], c = bid[a];
        for (int b = p + 1; b <= c; b++) start[b] = a;
    }
}

// ---------------------------------------------------------------------------
// segment-mean pooling: one warp per block
// ---------------------------------------------------------------------------
__global__ void k_pool(const float* __restrict__ H, const float* __restrict__ Z,
                       const int* __restrict__ start, float* __restrict__ h,
                       float* __restrict__ zc, float* __restrict__ outHb) {
    int gt = blockIdx.x * blockDim.x + threadIdx.x;
    int b = gt >> 5;
    int lane = gt & 31;
    if (b >= NBLK) return;
    int lo = start[b], hi = start[b + 1];
    float4 hs = make_float4(0.f, 0.f, 0.f, 0.f);
    for (int a = lo; a < hi; a++) {
        float4 v = *(const float4*)&H[(size_t)a * HID + lane * 4];
        hs.x += v.x; hs.y += v.y; hs.z += v.z; hs.w += v.w;
    }
    float zx = 0.f, zy = 0.f, zz = 0.f;
    for (int a = lo + lane; a < hi; a += 32) {
        zx += Z[a * 3 + 0]; zy += Z[a * 3 + 1]; zz += Z[a * 3 + 2];
    }
#pragma unroll
    for (int o = 16; o > 0; o >>= 1) {
        zx += __shfl_xor_sync(0xffffffffu, zx, o);
        zy += __shfl_xor_sync(0xffffffffu, zy, o);
        zz += __shfl_xor_sync(0xffffffffu, zz, o);
    }
    float cnt = (float)(hi - lo);
    float inv = 1.0f / fmaxf(cnt, 1.0f);
    hs.x *= inv; hs.y *= inv; hs.z *= inv; hs.w *= inv;
    *(float4*)&h[(size_t)b * HID + lane * 4] = hs;
    *(float4*)&outHb[(size_t)b * HID + lane * 4] = hs;
    if (lane == 0) {
        zc[b * 4 + 0] = zx * inv;
        zc[b * 4 + 1] = zy * inv;
        zc[b * 4 + 2] = zz * inv;
        zc[b * 4 + 3] = cnt;
    }
}

// ---------------------------------------------------------------------------
// counting sort of edges by dst
// ---------------------------------------------------------------------------
__global__ void k_hist(const int* __restrict__ edges, int* __restrict__ cnt) {
    int e = blockIdx.x * blockDim.x + threadIdx.x;
    if (e < NE) atomicAdd(&cnt[edges[NE + e]], 1);
}

__global__ void k_scan1(const int* __restrict__ cnt, int* __restrict__ offs,
                        int* __restrict__ tops) {
    __shared__ int sh[512];
    int i = blockIdx.x * 512 + threadIdx.x;
    int v = (i < NBLK) ? cnt[i] : 0;
    sh[threadIdx.x] = v;
    __syncthreads();
#pragma unroll
    for (int off = 1; off < 512; off <<= 1) {
        int t = 0;
        if (threadIdx.x >= off) t = sh[threadIdx.x - off];
        __syncthreads();
        if (threadIdx.x >= off) sh[threadIdx.x] += t;
        __syncthreads();
    }
    if (i < NBLK) offs[i] = sh[threadIdx.x] - v;
    if (threadIdx.x == 511) tops[blockIdx.x] = sh[511];
}

__global__ void k_scan2(int* __restrict__ tops) {
    __shared__ int sh[128];
    int v = (threadIdx.x < NTOPS) ? tops[threadIdx.x] : 0;
    sh[threadIdx.x] = v;
    __syncthreads();
#pragma unroll
    for (int off = 1; off < 128; off <<= 1) {
        int t = 0;
        if (threadIdx.x >= off) t = sh[threadIdx.x - off];
        __syncthreads();
        if (threadIdx.x >= off) sh[threadIdx.x] += t;
        __syncthreads();
    }
    if (threadIdx.x < NTOPS) tops[threadIdx.x] = sh[threadIdx.x] - v;
}

__global__ void k_scan3(int* __restrict__ offs, const int* __restrict__ tops) {
    int i = blockIdx.x * 512 + threadIdx.x;
    if (i < NBLK) offs[i] += tops[blockIdx.x];
}

// scatter: sorted position gets (src, nearest table row index)
__global__ void k_scat(const int* __restrict__ edges, int* __restrict__ offs,
                       const float* __restrict__ zc, int2* __restrict__ ssit) {
    int e = blockIdx.x * blockDim.x + threadIdx.x;
    if (e >= NE) return;
    int s = edges[e];
    int d = edges[NE + e];
    int pos = atomicAdd(&offs[d], 1);
    float dx = zc[s * 4 + 0] - zc[d * 4 + 0];
    float dy = zc[s * 4 + 1] - zc[d * 4 + 1];
    float dz = zc[s * 4 + 2] - zc[d * 4 + 2];
    float dd = sqrtf(dx * dx + dy * dy + dz * dz + 1e-12f);
    int it = (int)(dd * TABSCALE + 0.5f);
    if (it > TABN - 1) it = TABN - 1;
    ssit[pos] = make_int2(s, it);
}
// after k_scat, offs[d] holds the END offset of dst-segment d.

// ---------------------------------------------------------------------------
// build fp16 lookup table T[l][g][j] = rbf(g/1024) @ Wc[l]
// ---------------------------------------------------------------------------
__global__ void k_table(const float* __restrict__ Wc, __half* __restrict__ T) {
    __shared__ float rb[8][64];
    int g0 = blockIdx.x * 8, l = blockIdx.y;
    int tid = threadIdx.x;
    for (int i = tid; i < 8 * 64; i += 256) {
        int gi = i >> 6;
        int k = i & 63;
        float dd = (float)(g0 + gi) * (1.0f / TABSCALE)
                 - (6.0f / 63.0f) * (float)k;
        rb[gi][k] = __expf(-10.0f * dd * dd);
    }
    __syncthreads();
    const float* W = Wc + (size_t)l * 64 * 256;
    float acc[8];
#pragma unroll
    for (int gi = 0; gi < 8; gi++) acc[gi] = 0.f;
#pragma unroll 8
    for (int k = 0; k < 64; k++) {
        float w = W[k * 256 + tid];
#pragma unroll
        for (int gi = 0; gi < 8; gi++) acc[gi] += rb[gi][k] * w;
    }
    __half* out = T + ((size_t)l * TABN + g0) * 256 + tid;
#pragma unroll
    for (int gi = 0; gi < 8; gi++) out[gi * 256] = __float2half(acc[gi]);
}

// ---------------------------------------------------------------------------
// tf32 tensor GEMM: C[M,N] = A[M,K] @ B[K,N], B pre-converted to tf32 bits.
// BM=128 BN=128 BK=32, 256 threads, warps 2x4, warp tile 64x32.
// block.x >= ntiles0 -> (B1,C1). epi==1: C += silu(acc).
// Requires K%32==0, N%128==0.
// ---------------------------------------------------------------------------
__global__ void __launch_bounds__(256)
k_gemm(const float* __restrict__ A, const unsigned* __restrict__ B0,
       const unsigned* __restrict__ B1, float* __restrict__ C0,
       float* __restrict__ C1, int M, int N, int K, int epi, int ntiles0) {
    __shared__ unsigned As[128 * 36];
    __shared__ unsigned Bs[32 * 136];
    int tid = threadIdx.x;
    int warp = tid >> 5, lane = tid & 31;
    int gid = lane >> 2, tig = lane & 3;
    int wm = (warp & 1) * 64, wn = (warp >> 1) * 32;
    int rowBase = blockIdx.y * 128;
    int bx = blockIdx.x;
    const unsigned* B = B0;
    float* C = C0;
    if (bx >= ntiles0) { B = B1; C = C1; bx -= ntiles0; }
    int colBase = bx * 128;

    int ar = tid >> 3, ac = (tid & 7) * 4;   // A: 32 rows x 8 quads
    int br = tid >> 5, bc = (tid & 31) * 4;  // B: 8 rows x 32 quads

    float4 av[4];
    uint4 bv[4];
#pragma unroll
    for (int i = 0; i < 4; i++) {
        int r = rowBase + ar + i * 32;
        av[i] = (r < M) ? *(const float4*)&A[(size_t)r * K + ac]
                        : make_float4(0.f, 0.f, 0.f, 0.f);
    }
#pragma unroll
    for (int i = 0; i < 4; i++)
        bv[i] = *(const uint4*)&B[(size_t)(br + i * 8) * N + colBase + bc];

    float acc[4][4][4];
#pragma unroll
    for (int mt = 0; mt < 4; mt++)
#pragma unroll
        for (int nn = 0; nn < 4; nn++)
#pragma unroll
            for (int q = 0; q < 4; q++) acc[mt][nn][q] = 0.f;

    for (int k0 = 0; k0 < K; k0 += 32) {
#pragma unroll
        for (int i = 0; i < 4; i++) {
            uint4 u;
            u.x = cvt_tf32(av[i].x); u.y = cvt_tf32(av[i].y);
            u.z = cvt_tf32(av[i].z); u.w = cvt_tf32(av[i].w);
            *(uint4*)&As[(ar + i * 32) * 36 + ac] = u;
        }
#pragma unroll
        for (int i = 0; i < 4; i++)
            *(uint4*)&Bs[(br + i * 8) * 136 + bc] = bv[i];
        __syncthreads();
        if (k0 + 32 < K) {
#pragma unroll
            for (int i = 0; i < 4; i++) {
                int r = rowBase + ar + i * 32;
                av[i] = (r < M)
                    ? *(const float4*)&A[(size_t)r * K + k0 + 32 + ac]
                    : make_float4(0.f, 0.f, 0.f, 0.f);
            }
#pragma unroll
            for (int i = 0; i < 4; i++)
                bv[i] = *(const uint4*)
                    &B[(size_t)(k0 + 32 + br + i * 8) * N + colBase + bc];
        }
#pragma unroll
        for (int kk = 0; kk < 4; kk++) {
            unsigned a[4][4], b[4][2];
#pragma unroll
            for (int mt = 0; mt < 4; mt++) {
                int r = wm + mt * 16 + gid;
                a[mt][0] = As[r * 36 + kk * 8 + tig];
                a[mt][1] = As[(r + 8) * 36 + kk * 8 + tig];
                a[mt][2] = As[r * 36 + kk * 8 + tig + 4];
                a[mt][3] = As[(r + 8) * 36 + kk * 8 + tig + 4];
            }
#pragma unroll
            for (int nn = 0; nn < 4; nn++) {
                b[nn][0] = Bs[(kk * 8 + tig) * 136 + wn + nn * 8 + gid];
                b[nn][1] = Bs[(kk * 8 + tig + 4) * 136 + wn + nn * 8 + gid];
            }
#pragma unroll
            for (int mt = 0; mt < 4; mt++)
#pragma unroll
                for (int nn = 0; nn < 4; nn++)
                    mma_tf32(acc[mt][nn], a[mt], b[nn]);
        }
        __syncthreads();
    }

#pragma unroll
    for (int mt = 0; mt < 4; mt++) {
#pragma unroll
        for (int nn = 0; nn < 4; nn++) {
            int r0 = rowBase + wm + mt * 16 + gid;
            int r1 = r0 + 8;
            int c = colBase + wn + nn * 8 + 2 * tig;
            if (r0 < M) {
                size_t idx = (size_t)r0 * N + c;
                if (epi == 1) {
                    C[idx]     += silu_f(acc[mt][nn][0]);
                    C[idx + 1] += silu_f(acc[mt][nn][1]);
                } else {
                    C[idx]     = acc[mt][nn][0];
                    C[idx + 1] = acc[mt][nn][1];
                }
            }
            if (r1 < M) {
                size_t idx = (size_t)r1 * N + c;
                if (epi == 1) {
                    C[idx]     += silu_f(acc[mt][nn][2]);
                    C[idx + 1] += silu_f(acc[mt][nn][3]);
                } else {
                    C[idx]     = acc[mt][nn][2];
                    C[idx + 1] = acc[mt][nn][3];
                }
            }
        }
    }
}

// ---------------------------------------------------------------------------
// edge+aggregate kernel: TWO warps per dst block (128 cols each).
// agg[d] = sum_{e in seg(d)} silu(A[src_e] + B[d] + T[row_e])   (T in fp16)
// ---------------------------------------------------------------------------
__global__ void __launch_bounds__(256)
k_edge_lut(const int2* __restrict__ ssit, const int* __restrict__ eend,
           const __half* __restrict__ Tl, const float* __restrict__ Ag,
           const float* __restrict__ Bg, float* __restrict__ agg) {
    int gw = (blockIdx.x * blockDim.x + threadIdx.x) >> 5;
    int d = gw >> 1;
    int hh = gw & 1;
    int lane = threadIdx.x & 31;
    if (d >= NBLK) return;
    int lo = (d > 0) ? eend[d - 1] : 0;
    int hi = eend[d];
    int c = hh * 128 + lane * 4;

    float4 acc = make_float4(0.f, 0.f, 0.f, 0.f);

    if (lo < hi) {
        float4 b = *(const float4*)&Bg[(size_t)d * 256 + c];
        for (int e = lo; e < hi; e++) {
            int2 se = ssit[e];
            float4 a = *(const float4*)&Ag[((size_t)se.x << 8) + c];
            uint2 raw = *(const uint2*)&Tl[((size_t)se.y << 8) + c];
            float2 f0 = __half22float2(*(__half2*)&raw.x);
            float2 f1 = __half22float2(*(__half2*)&raw.y);
            acc.x += silu_f(a.x + b.x + f0.x);
            acc.y += silu_f(a.y + b.y + f0.y);
            acc.z += silu_f(a.z + b.z + f1.x);
            acc.w += silu_f(a.w + b.w + f1.y);
        }
    }
    *(float4*)&agg[(size_t)d * 256 + c] = acc;
}

// ---------------------------------------------------------------------------
__global__ void k_rownorm_scatter(const float* __restrict__ tmp,
                                  const int* __restrict__ batch_id,
                                  float* __restrict__ out_block,
                                  float* __restrict__ gacc) {
    int gt = blockIdx.x * blockDim.x + threadIdx.x;
    int r = gt >> 5;
    int lane = gt & 31;
    if (r >= NBLK) return;
    float4 v = *(const float4*)&tmp[(size_t)r * HID + lane * 4];
    float ss = v.x * v.x + v.y * v.y + v.z * v.z + v.w * v.w;
#pragma unroll
    for (int o = 16; o > 0; o >>= 1) ss += __shfl_xor_sync(0xffffffffu, ss, o);
    float inv = 1.0f / fmaxf(sqrtf(ss), 1e-12f);
    int g = batch_id[r];
    float4 nv = make_float4(v.x * inv, v.y * inv, v.z * inv, v.w * inv);
    *(float4*)&out_block[(size_t)r * HID + lane * 4] = nv;
    red4(&gacc[g * HID + lane * 4], nv);
}

__global__ void k_graphnorm(const float* __restrict__ gacc,
                            float* __restrict__ out_graph) {
    int gt = blockIdx.x * blockDim.x + threadIdx.x;
    int r = gt >> 5;
    int lane = gt & 31;
    if (r >= NG) return;
    float4 v = *(const float4*)&gacc[r * HID + lane * 4];
    float ss = v.x * v.x + v.y * v.y + v.z * v.z + v.w * v.w;
#pragma unroll
    for (int o = 16; o > 0; o >>= 1) ss += __shfl_xor_sync(0xffffffffu, ss, o);
    float inv = 1.0f / fmaxf(sqrtf(ss), 1e-12f);
    float4 nv = make_float4(v.x * inv, v.y * inv, v.z * inv, v.w * inv);
    *(float4*)&out_graph[r * HID + lane * 4] = nv;
}

// ---------------------------------------------------------------------------
extern "C" void kernel_launch(void* const* d_in, const int* in_sizes, int n_in,
                              void* d_out, int out_size) {
    const float* H      = (const float*)d_in[0];
    const float* Z      = (const float*)d_in[1];
    const float* W_rbf  = (const float*)d_in[2];
    const float* Wm1    = (const float*)d_in[3];
    const float* Wm2    = (const float*)d_in[4];
    const float* We     = (const float*)d_in[5];
    const float* Wupd   = (const float*)d_in[6];
    const float* W_out  = (const float*)d_in[7];
    const int*   block_id = (const int*)d_in[8];
    const int*   batch_id = (const int*)d_in[9];
    const int*   edges    = (const int*)d_in[10];

    float* out = (float*)d_out;
    float* out_Hb    = out;
    float* out_block = out + (size_t)NBLK * HID;
    float* out_graph = out + 2 * (size_t)NBLK * HID;

    void* scrv = nullptr;
    cudaGetSymbolAddress(&scrv, g_scratch);
    float* scr  = (float*)scrv;
    float* s_h    = scr + OFF_H;
    float* s_zc   = scr + OFF_ZC;
    float* s_A    = scr + OFF_A;
    float* s_B    = scr + OFF_B;
    float* s_agg  = scr + OFF_AGG;
    __half* s_tab = (__half*)(scr + OFF_TAB);
    float* s_Wc   = scr + OFF_WC;
    float* s_gacc = scr + OFF_GACC;
    int*   s_start = (int*)(scr + OFF_START);
    int*   s_cnt   = (int*)(scr + OFF_CNT);
    int*   s_tops  = (int*)(scr + OFF_TOPS);
    int2*  s_ssit  = (int2*)(scr + OFF_SSIT);
    unsigned* s_wtf = (unsigned*)(scr + OFF_WTF);

    dim3 gridAB(4, (NBLK + 127) / 128);   // 2 tiles Wm1 + 2 tiles Wm2
    dim3 gridUpd(1, (NBLK + 127) / 128);  // N=128, one tile

    // 0: convert Wm1+Wm2 to tf32 (3 layers contiguous each)
    k_cvt2<<<(3 * HID * EDGEF + 255) / 256, 256>>>(
        Wm1, Wm2, s_wtf + WTF_WM1(0), s_wtf + WTF_WM2(0),
        3 * HID * EDGEF, 3 * HID * EDGEF);
    // 1: bounds, 2: pool
    k_bounds<<<(NATM + 256) / 256, 256>>>(block_id, s_start);
    k_pool<<<(NBLK * 32 + 255) / 256, 256>>>(H, Z, s_start, s_h, s_zc, out_Hb);
    // 3: layer-0 A/B GEMM (ncu slot)
    k_gemm<<<gridAB, 256>>>(s_h, s_wtf + WTF_WM1(0), s_wtf + WTF_WM2(0),
                            s_A, s_B, NBLK, EDGEF, HID, 0, 2);

    // remaining weight conversions
    k_cvt2<<<(3 * EDGEF * EDGEF + 255) / 256, 256>>>(
        We, Wupd, s_wtf + WTF_WE(0), s_wtf + WTF_WUPD(0),
        3 * EDGEF * EDGEF, 3 * EDGEF * HID);
    k_cvt2<<<(HID * HID + 255) / 256, 256>>>(
        W_out, nullptr, s_wtf + WTF_WOUT, nullptr, HID * HID, 0);

    // Wc[l] = W_rbf @ We_tf32[l]
    for (int l = 0; l < NLAY; l++) {
        k_gemm<<<dim3(2, 1), 256>>>(W_rbf, s_wtf + WTF_WE(l), nullptr,
                                    s_Wc + (size_t)l * 64 * 256, nullptr,
                                    64, 256, 256, 0, 2);
    }

    // table + edge sort + misc
    k_table<<<dim3(TABN / 8, NLAY), 256>>>(s_Wc, s_tab);
    k_zero4<<<32, 256>>>((float*)s_cnt, 50016 / 4);
    k_hist<<<(NE + 255) / 256, 256>>>(edges, s_cnt);
    k_scan1<<<NTOPS, 512>>>(s_cnt, s_cnt, s_tops);
    k_scan2<<<1, 128>>>(s_tops);
    k_scan3<<<NTOPS, 512>>>(s_cnt, s_tops);
    k_scat<<<(NE + 255) / 256, 256>>>(edges, s_cnt, s_zc, s_ssit);
    k_zero4<<<8, 256>>>(s_gacc, (NG * HID) / 4);

    for (int l = 0; l < NLAY; l++) {
        if (l > 0) {
            k_gemm<<<gridAB, 256>>>(s_h, s_wtf + WTF_WM1(l), s_wtf + WTF_WM2(l),
                                    s_A, s_B, NBLK, EDGEF, HID, 0, 2);
        }
        k_edge_lut<<<(NBLK * 64 + 255) / 256, 256>>>(
            s_ssit, s_cnt, s_tab + (size_t)l * TABN * 256, s_A, s_B, s_agg);
        k_gemm<<<gridUpd, 256>>>(s_agg, s_wtf + WTF_WUPD(l), nullptr,
                                 s_h, nullptr, NBLK, HID, EDGEF, 1, 1);
    }

    // block_repr = l2norm(h @ W_out)
    k_gemm<<<gridUpd, 256>>>(s_h, s_wtf + WTF_WOUT, nullptr, s_A, nullptr,
                             NBLK, HID, HID, 0, 1);
    k_rownorm_scatter<<<(NBLK * 32 + 255) / 256, 256>>>(s_A, batch_id,
                                                        out_block, s_gacc);
    k_graphnorm<<<(NG * 32 + 255) / 256, 256>>>(s_gacc, out_graph);
}

// round 12
// speedup vs baseline: 1.0696x; 1.0355x over previous
#include <cuda_runtime.h>
#include <cuda_bf16.h>
#include <cuda_fp16.h>
#include <math.h>

#define NATM 200000
#define NBLK 50000
#define NE   450000
#define NG   64
#define HID  128
#define RAD  64
#define EDGEF 256
#define NLAY 3
#define TABN 8192          // nearest-neighbor table, spacing 1/1024 over [0,8)
#define TABSCALE 1024.0f

// ---- scratch layout (single __device__ buffer, float units) ----
static const size_t OFF_H     = 0;          // float  [NBLK*128]
static const size_t OFF_HT    = 6400000;    // uint   [NBLK*128] tf32 mirror
static const size_t OFF_ZC    = 12800000;   // float  [NBLK*4]
static const size_t OFF_A     = 13000000;   // half   [NBLK*256]
static const size_t OFF_B     = 19400000;   // half   [NBLK*256]
static const size_t OFF_AGG   = 25800000;   // uint   [NBLK*256] tf32 bits / fp32 tmp
static const size_t OFF_TAB   = 38600000;   // half   [3*8192*256]
static const size_t OFF_WC    = 41745728;   // float  [3*64*256]
static const size_t OFF_GACC  = 41794880;   // float  [64*128]
static const size_t OFF_START = 41803072;   // int    [NBLK+1]
static const size_t OFF_CNT   = 41853088;   // int    [NBLK]
static const size_t OFF_TOPS  = 41903104;   // int    [128]
static const size_t OFF_SSIT  = 41903232;   // int2   [NE]
static const size_t OFF_WTF   = 42803232;   // uint   [524288] tf32 weights
static const size_t SCR_TOTAL = 43327520;

// tf32 weight sub-offsets (relative to OFF_WTF)
#define WTF_WE(l)   ((size_t)(l) * 65536)
#define WTF_WM1(l)  (196608 + (size_t)(l) * 32768)
#define WTF_WM2(l)  (294912 + (size_t)(l) * 32768)
#define WTF_WUPD(l) (393216 + (size_t)(l) * 32768)
#define WTF_WOUT    (491520)
#define WTF_WRBF    (507904)

__device__ __align__(16) float g_scratch[SCR_TOTAL];

#define NTOPS 98   // ceil(NBLK/512)

__device__ __forceinline__ float silu_f(float x) {
    return x / (1.0f + __expf(-x));
}

__device__ __forceinline__ unsigned cvt_tf32(float f) {
    unsigned u;
    asm("cvt.rna.tf32.f32 %0, %1;" : "=r"(u) : "f"(f));
    return u;
}

__device__ __forceinline__ void mma_tf32(float* c, const unsigned* a,
                                         const unsigned* b) {
    asm volatile(
        "mma.sync.aligned.m16n8k8.row.col.f32.tf32.tf32.f32 "
        "{%0,%1,%2,%3}, {%4,%5,%6,%7}, {%8,%9}, {%0,%1,%2,%3};"
        : "+f"(c[0]), "+f"(c[1]), "+f"(c[2]), "+f"(c[3])
        : "r"(a[0]), "r"(a[1]), "r"(a[2]), "r"(a[3]), "r"(b[0]), "r"(b[1]));
}

__device__ __forceinline__ void red4(float* p, float4 v) {
    asm volatile("red.global.add.v4.f32 [%0], {%1,%2,%3,%4};"
                 :: "l"(p), "f"(v.x), "f"(v.y), "f"(v.z), "f"(v.w)
                 : "memory");
}

// ---------------------------------------------------------------------------
__global__ void k_zero4(float* __restrict__ p, int n4) {
    float4 z = make_float4(0.f, 0.f, 0.f, 0.f);
    for (int i = blockIdx.x * blockDim.x + threadIdx.x; i < n4;
         i += gridDim.x * blockDim.x) {
        ((float4*)p)[i] = z;
    }
}

// convert two fp32 tensors to tf32 bit patterns (independent sizes)
__global__ void k_cvt2(const float* __restrict__ s0, const float* __restrict__ s1,
                       unsigned* __restrict__ d0, unsigned* __restrict__ d1,
                       int n0, int n1) {
    int i = blockIdx.x * blockDim.x + threadIdx.x;
    if (i < n0) d0[i] = cvt_tf32(s0[i]);
    if (i < n1) d1[i] = cvt_tf32(s1[i]);
}

// ---------------------------------------------------------------------------
// segment boundaries of sorted block_id
// ---------------------------------------------------------------------------
__global__ void k_bounds(const int* __restrict__ bid, int* __restrict__ start) {
    int a = blockIdx.x * blockDim.x + threadIdx.x;
    if (a > NATM) return;
    if (a == 0) {
        int c = bid[0];
        for (int b = 0; b <= c; b++) start[b] = 0;
    } else if (a == NATM) {
        int p = bid[NATM - 1];
        for (int b = p + 1; b <= NBLK; b++) start[b] = NATM;
    } else {
        int p = bid[a - 1], c = bid[a];
        for (int b = p + 1; b <= c; b++) start[b] = a;
    }
}

// ---------------------------------------------------------------------------
// segment-mean pooling: one warp per block; writes h fp32 + tf32 mirror
// ---------------------------------------------------------------------------
__global__ void k_pool(const float* __restrict__ H, const float* __restrict__ Z,
                       const int* __restrict__ start, float* __restrict__ h,
                       unsigned* __restrict__ ht, float* __restrict__ zc,
                       float* __restrict__ outHb) {
    int gt = blockIdx.x * blockDim.x + threadIdx.x;
    int b = gt >> 5;
    int lane = gt & 31;
    if (b >= NBLK) return;
    int lo = start[b], hi = start[b + 1];
    float4 hs = make_float4(0.f, 0.f, 0.f, 0.f);
    for (int a = lo; a < hi; a++) {
        float4 v = *(const float4*)&H[(size_t)a * HID + lane * 4];
        hs.x += v.x; hs.y += v.y; hs.z += v.z; hs.w += v.w;
    }
    float zx = 0.f, zy = 0.f, zz = 0.f;
    for (int a = lo + lane; a < hi; a += 32) {
        zx += Z[a * 3 + 0]; zy += Z[a * 3 + 1]; zz += Z[a * 3 + 2];
    }
#pragma unroll
    for (int o = 16; o > 0; o >>= 1) {
        zx += __shfl_xor_sync(0xffffffffu, zx, o);
        zy += __shfl_xor_sync(0xffffffffu, zy, o);
        zz += __shfl_xor_sync(0xffffffffu, zz, o);
    }
    float cnt = (float)(hi - lo);
    float inv = 1.0f / fmaxf(cnt, 1.0f);
    hs.x *= inv; hs.y *= inv; hs.z *= inv; hs.w *= inv;
    size_t idx = (size_t)b * HID + lane * 4;
    *(float4*)&h[idx] = hs;
    *(float4*)&outHb[idx] = hs;
    uint4 m;
    m.x = cvt_tf32(hs.x); m.y = cvt_tf32(hs.y);
    m.z = cvt_tf32(hs.z); m.w = cvt_tf32(hs.w);
    *(uint4*)&ht[idx] = m;
    if (lane == 0) {
        zc[b * 4 + 0] = zx * inv;
        zc[b * 4 + 1] = zy * inv;
        zc[b * 4 + 2] = zz * inv;
        zc[b * 4 + 3] = cnt;
    }
}

// ---------------------------------------------------------------------------
// counting sort of edges by dst
// ---------------------------------------------------------------------------
__global__ void k_hist(const int* __restrict__ edges, int* __restrict__ cnt) {
    int e = blockIdx.x * blockDim.x + threadIdx.x;
    if (e < NE) atomicAdd(&cnt[edges[NE + e]], 1);
}

__global__ void k_scan1(const int* __restrict__ cnt, int* __restrict__ offs,
                        int* __restrict__ tops) {
    __shared__ int sh[512];
    int i = blockIdx.x * 512 + threadIdx.x;
    int v = (i < NBLK) ? cnt[i] : 0;
    sh[threadIdx.x] = v;
    __syncthreads();
#pragma unroll
    for (int off = 1; off < 512; off <<= 1) {
        int t = 0;
        if (threadIdx.x >= off) t = sh[threadIdx.x - off];
        __syncthreads();
        if (threadIdx.x >= off) sh[threadIdx.x] += t;
        __syncthreads();
    }
    if (i < NBLK) offs[i] = sh[threadIdx.x] - v;
    if (threadIdx.x == 511) tops[blockIdx.x] = sh[511];
}

__global__ void k_scan2(int* __restrict__ tops) {
    __shared__ int sh[128];
    int v = (threadIdx.x < NTOPS) ? tops[threadIdx.x] : 0;
    sh[threadIdx.x] = v;
    __syncthreads();
#pragma unroll
    for (int off = 1; off < 128; off <<= 1) {
        int t = 0;
        if (threadIdx.x >= off) t = sh[threadIdx.x - off];
        __syncthreads();
        if (threadIdx.x >= off) sh[threadIdx.x] += t;
        __syncthreads();
    }
    if (threadIdx.x < NTOPS) tops[threadIdx.x] = sh[threadIdx.x] - v;
}

__global__ void k_scan3(int* __restrict__ offs, const int* __restrict__ tops) {
    int i = blockIdx.x * 512 + threadIdx.x;
    if (i < NBLK) offs[i] += tops[blockIdx.x];
}

// scatter: sorted position gets (src, nearest table row index)
__global__ void k_scat(const int* __restrict__ edges, int* __restrict__ offs,
                       const float* __restrict__ zc, int2* __restrict__ ssit) {
    int e = blockIdx.x * blockDim.x + threadIdx.x;
    if (e >= NE) return;
    int s = edges[e];
    int d = edges[NE + e];
    int pos = atomicAdd(&offs[d], 1);
    float dx = zc[s * 4 + 0] - zc[d * 4 + 0];
    float dy = zc[s * 4 + 1] - zc[d * 4 + 1];
    float dz = zc[s * 4 + 2] - zc[d * 4 + 2];
    float dd = sqrtf(dx * dx + dy * dy + dz * dz + 1e-12f);
    int it = (int)(dd * TABSCALE + 0.5f);
    if (it > TABN - 1) it = TABN - 1;
    ssit[pos] = make_int2(s, it);
}
// after k_scat, offs[d] holds the END offset of dst-segment d.

// ---------------------------------------------------------------------------
// build fp16 lookup table T[l][g][j] = rbf(g/1024) @ Wc[l]
// ---------------------------------------------------------------------------
__global__ void k_table(const float* __restrict__ Wc, __half* __restrict__ T) {
    __shared__ float rb[8][64];
    int g0 = blockIdx.x * 8, l = blockIdx.y;
    int tid = threadIdx.x;
    for (int i = tid; i < 8 * 64; i += 256) {
        int gi = i >> 6;
        int k = i & 63;
        float dd = (float)(g0 + gi) * (1.0f / TABSCALE)
                 - (6.0f / 63.0f) * (float)k;
        rb[gi][k] = __expf(-10.0f * dd * dd);
    }
    __syncthreads();
    const float* W = Wc + (size_t)l * 64 * 256;
    float acc[8];
#pragma unroll
    for (int gi = 0; gi < 8; gi++) acc[gi] = 0.f;
#pragma unroll 8
    for (int k = 0; k < 64; k++) {
        float w = W[k * 256 + tid];
#pragma unroll
        for (int gi = 0; gi < 8; gi++) acc[gi] += rb[gi][k] * w;
    }
    __half* out = T + ((size_t)l * TABN + g0) * 256 + tid;
#pragma unroll
    for (int gi = 0; gi < 8; gi++) out[gi * 256] = __float2half(acc[gi]);
}

// ---------------------------------------------------------------------------
// tf32 tensor GEMM: A and B are PRE-CONVERTED tf32 bit patterns.
// BM=128 BN=128 BK=32, 256 threads, warps 2x4, warp tile 64x32.
// epi==0: C fp32 store. epi==2: C fp16 store. epi==1: C0(fp32) += silu(acc),
//         C1 = tf32 mirror of updated C0 (no bx output selection).
// block.x >= ntiles0 -> (B1, C1-as-output) for epi 0/2.
// ---------------------------------------------------------------------------
__global__ void __launch_bounds__(256)
k_gemm(const unsigned* __restrict__ A, const unsigned* __restrict__ B0,
       const unsigned* __restrict__ B1, void* C0v, void* C1v,
       int M, int N, int K, int epi, int ntiles0) {
    __shared__ unsigned As[128 * 36];
    __shared__ unsigned Bs[32 * 136];
    int tid = threadIdx.x;
    int warp = tid >> 5, lane = tid & 31;
    int gid = lane >> 2, tig = lane & 3;
    int wm = (warp & 1) * 64, wn = (warp >> 1) * 32;
    int rowBase = blockIdx.y * 128;
    int bx = blockIdx.x;
    const unsigned* B = B0;
    int outSel = 0;
    if (bx >= ntiles0) { B = B1; outSel = 1; bx -= ntiles0; }
    int colBase = bx * 128;

    int ar = tid >> 3, ac = (tid & 7) * 4;   // A: 32 rows x 8 quads
    int br = tid >> 5, bc = (tid & 31) * 4;  // B: 8 rows x 32 quads

    uint4 av[4], bv[4];
#pragma unroll
    for (int i = 0; i < 4; i++) {
        int r = rowBase + ar + i * 32;
        av[i] = (r < M) ? *(const uint4*)&A[(size_t)r * K + ac]
                        : make_uint4(0, 0, 0, 0);
    }
#pragma unroll
    for (int i = 0; i < 4; i++)
        bv[i] = *(const uint4*)&B[(size_t)(br + i * 8) * N + colBase + bc];

    float acc[4][4][4];
#pragma unroll
    for (int mt = 0; mt < 4; mt++)
#pragma unroll
        for (int nn = 0; nn < 4; nn++)
#pragma unroll
            for (int q = 0; q < 4; q++) acc[mt][nn][q] = 0.f;

    for (int k0 = 0; k0 < K; k0 += 32) {
#pragma unroll
        for (int i = 0; i < 4; i++)
            *(uint4*)&As[(ar + i * 32) * 36 + ac] = av[i];
#pragma unroll
        for (int i = 0; i < 4; i++)
            *(uint4*)&Bs[(br + i * 8) * 136 + bc] = bv[i];
        __syncthreads();
        if (k0 + 32 < K) {
#pragma unroll
            for (int i = 0; i < 4; i++) {
                int r = rowBase + ar + i * 32;
                av[i] = (r < M)
                    ? *(const uint4*)&A[(size_t)r * K + k0 + 32 + ac]
                    : make_uint4(0, 0, 0, 0);
            }
#pragma unroll
            for (int i = 0; i < 4; i++)
                bv[i] = *(const uint4*)
                    &B[(size_t)(k0 + 32 + br + i * 8) * N + colBase + bc];
        }
#pragma unroll
        for (int kk = 0; kk < 4; kk++) {
            unsigned a[4][4], b[4][2];
#pragma unroll
            for (int mt = 0; mt < 4; mt++) {
                int r = wm + mt * 16 + gid;
                a[mt][0] = As[r * 36 + kk * 8 + tig];
                a[mt][1] = As[(r + 8) * 36 + kk * 8 + tig];
                a[mt][2] = As[r * 36 + kk * 8 + tig + 4];
                a[mt][3] = As[(r + 8) * 36 + kk * 8 + tig + 4];
            }
#pragma unroll
            for (int nn = 0; nn < 4; nn++) {
                b[nn][0] = Bs[(kk * 8 + tig) * 136 + wn + nn * 8 + gid];
                b[nn][1] = Bs[(kk * 8 + tig + 4) * 136 + wn + nn * 8 + gid];
            }
#pragma unroll
            for (int mt = 0; mt < 4; mt++)
#pragma unroll
                for (int nn = 0; nn < 4; nn++)
                    mma_tf32(acc[mt][nn], a[mt], b[nn]);
        }
        __syncthreads();
    }

#pragma unroll
    for (int mt = 0; mt < 4; mt++) {
#pragma unroll
        for (int nn = 0; nn < 4; nn++) {
            int c = colBase + wn + nn * 8 + 2 * tig;
#pragma unroll
            for (int half = 0; half < 2; half++) {
                int r = rowBase + wm + mt * 16 + gid + half * 8;
                if (r >= M) continue;
                float v0 = acc[mt][nn][half * 2 + 0];
                float v1 = acc[mt][nn][half * 2 + 1];
                size_t idx = (size_t)r * N + c;
                if (epi == 0) {
                    float* C = outSel ? (float*)C1v : (float*)C0v;
                    C[idx] = v0;
                    C[idx + 1] = v1;
                } else if (epi == 2) {
                    __half* C = outSel ? (__half*)C1v : (__half*)C0v;
                    *(__half2*)&C[idx] = __floats2half2_rn(v0, v1);
                } else {
                    float* Ch = (float*)C0v;
                    unsigned* Cm = (unsigned*)C1v;
                    float n0 = Ch[idx] + silu_f(v0);
                    float n1 = Ch[idx + 1] + silu_f(v1);
                    Ch[idx] = n0; Ch[idx + 1] = n1;
                    Cm[idx] = cvt_tf32(n0); Cm[idx + 1] = cvt_tf32(n1);
                }
            }
        }
    }
}

// ---------------------------------------------------------------------------
// edge+aggregate kernel: TWO warps per dst block (128 cols each).
// agg[d] = sum_{e in seg(d)} silu(A[src_e] + B[d] + T[row_e])
// A,B,T fp16; agg stored as tf32 bit patterns (consumed by upd GEMM).
// ---------------------------------------------------------------------------
__global__ void __launch_bounds__(256)
k_edge_lut(const int2* __restrict__ ssit, const int* __restrict__ eend,
           const __half* __restrict__ Tl, const __half* __restrict__ Ag,
           const __half* __restrict__ Bg, unsigned* __restrict__ agg) {
    int gw = (blockIdx.x * blockDim.x + threadIdx.x) >> 5;
    int d = gw >> 1;
    int hh = gw & 1;
    int lane = threadIdx.x & 31;
    if (d >= NBLK) return;
    int lo = (d > 0) ? eend[d - 1] : 0;
    int hi = eend[d];
    int c = hh * 128 + lane * 4;

    float4 acc = make_float4(0.f, 0.f, 0.f, 0.f);

    if (lo < hi) {
        uint2 braw = *(const uint2*)&Bg[(size_t)d * 256 + c];
        float2 b0 = __half22float2(*(__half2*)&braw.x);
        float2 b1 = __half22float2(*(__half2*)&braw.y);
        for (int e = lo; e < hi; e++) {
            int2 se = ssit[e];
            uint2 araw = *(const uint2*)&Ag[((size_t)se.x << 8) + c];
            uint2 traw = *(const uint2*)&Tl[((size_t)se.y << 8) + c];
            float2 a0 = __half22float2(*(__half2*)&araw.x);
            float2 a1 = __half22float2(*(__half2*)&araw.y);
            float2 t0 = __half22float2(*(__half2*)&traw.x);
            float2 t1 = __half22float2(*(__half2*)&traw.y);
            acc.x += silu_f(a0.x + b0.x + t0.x);
            acc.y += silu_f(a0.y + b0.y + t0.y);
            acc.z += silu_f(a1.x + b1.x + t1.x);
            acc.w += silu_f(a1.y + b1.y + t1.y);
        }
    }
    uint4 o;
    o.x = cvt_tf32(acc.x); o.y = cvt_tf32(acc.y);
    o.z = cvt_tf32(acc.z); o.w = cvt_tf32(acc.w);
    *(uint4*)&agg[(size_t)d * 256 + c] = o;
}

// ---------------------------------------------------------------------------
__global__ void k_rownorm_scatter(const float* __restrict__ tmp,
                                  const int* __restrict__ batch_id,
                                  float* __restrict__ out_block,
                                  float* __restrict__ gacc) {
    int gt = blockIdx.x * blockDim.x + threadIdx.x;
    int r = gt >> 5;
    int lane = gt & 31;
    if (r >= NBLK) return;
    float4 v = *(const float4*)&tmp[(size_t)r * HID + lane * 4];
    float ss = v.x * v.x + v.y * v.y + v.z * v.z + v.w * v.w;
#pragma unroll
    for (int o = 16; o > 0; o >>= 1) ss += __shfl_xor_sync(0xffffffffu, ss, o);
    float inv = 1.0f / fmaxf(sqrtf(ss), 1e-12f);
    int g = batch_id[r];
    float4 nv = make_float4(v.x * inv, v.y * inv, v.z * inv, v.w * inv);
    *(float4*)&out_block[(size_t)r * HID + lane * 4] = nv;
    red4(&gacc[g * HID + lane * 4], nv);
}

__global__ void k_graphnorm(const float* __restrict__ gacc,
                            float* __restrict__ out_graph) {
    int gt = blockIdx.x * blockDim.x + threadIdx.x;
    int r = gt >> 5;
    int lane = gt & 31;
    if (r >= NG) return;
    float4 v = *(const float4*)&gacc[r * HID + lane * 4];
    float ss = v.x * v.x + v.y * v.y + v.z * v.z + v.w * v.w;
#pragma unroll
    for (int o = 16; o > 0; o >>= 1) ss += __shfl_xor_sync(0xffffffffu, ss, o);
    float inv = 1.0f / fmaxf(sqrtf(ss), 1e-12f);
    float4 nv = make_float4(v.x * inv, v.y * inv, v.z * inv, v.w * inv);
    *(float4*)&out_graph[r * HID + lane * 4] = nv;
}

// ---------------------------------------------------------------------------
extern "C" void kernel_launch(void* const* d_in, const int* in_sizes, int n_in,
                              void* d_out, int out_size) {
    const float* H      = (const float*)d_in[0];
    const float* Z      = (const float*)d_in[1];
    const float* W_rbf  = (const float*)d_in[2];
    const float* Wm1    = (const float*)d_in[3];
    const float* Wm2    = (const float*)d_in[4];
    const float* We     = (const float*)d_in[5];
    const float* Wupd   = (const float*)d_in[6];
    const float* W_out  = (const float*)d_in[7];
    const int*   block_id = (const int*)d_in[8];
    const int*   batch_id = (const int*)d_in[9];
    const int*   edges    = (const int*)d_in[10];

    float* out = (float*)d_out;
    float* out_Hb    = out;
    float* out_block = out + (size_t)NBLK * HID;
    float* out_graph = out + 2 * (size_t)NBLK * HID;

    void* scrv = nullptr;
    cudaGetSymbolAddress(&scrv, g_scratch);
    float* scr  = (float*)scrv;
    float*    s_h    = scr + OFF_H;
    unsigned* s_ht   = (unsigned*)(scr + OFF_HT);
    float*    s_zc   = scr + OFF_ZC;
    __half*   s_A    = (__half*)(scr + OFF_A);
    __half*   s_B    = (__half*)(scr + OFF_B);
    unsigned* s_agg  = (unsigned*)(scr + OFF_AGG);
    float*    s_tmp  = (float*)(scr + OFF_AGG);   // reused after last layer
    __half*   s_tab  = (__half*)(scr + OFF_TAB);
    float*    s_Wc   = scr + OFF_WC;
    float*    s_gacc = scr + OFF_GACC;
    int*      s_start = (int*)(scr + OFF_START);
    int*      s_cnt   = (int*)(scr + OFF_CNT);
    int*      s_tops  = (int*)(scr + OFF_TOPS);
    int2*     s_ssit  = (int2*)(scr + OFF_SSIT);
    unsigned* s_wtf   = (unsigned*)(scr + OFF_WTF);

    dim3 gridAB(4, (NBLK + 127) / 128);   // 2 tiles Wm1 + 2 tiles Wm2
    dim3 gridUpd(1, (NBLK + 127) / 128);  // N=128, one tile

    // 0: convert Wm1+Wm2 to tf32
    k_cvt2<<<(3 * HID * EDGEF + 255) / 256, 256>>>(
        Wm1, Wm2, s_wtf + WTF_WM1(0), s_wtf + WTF_WM2(0),
        3 * HID * EDGEF, 3 * HID * EDGEF);
    // 1: bounds, 2: pool (writes h + tf32 mirror)
    k_bounds<<<(NATM + 256) / 256, 256>>>(block_id, s_start);
    k_pool<<<(NBLK * 32 + 255) / 256, 256>>>(H, Z, s_start, s_h, s_ht, s_zc,
                                             out_Hb);
    // 3: layer-0 A/B GEMM (ncu slot), fp16 outputs
    k_gemm<<<gridAB, 256>>>(s_ht, s_wtf + WTF_WM1(0), s_wtf + WTF_WM2(0),
                            s_A, s_B, NBLK, EDGEF, HID, 2, 2);

    // remaining weight conversions
    k_cvt2<<<(3 * EDGEF * EDGEF + 255) / 256, 256>>>(
        We, Wupd, s_wtf + WTF_WE(0), s_wtf + WTF_WUPD(0),
        3 * EDGEF * EDGEF, 3 * EDGEF * HID);
    k_cvt2<<<(HID * HID + 255) / 256, 256>>>(
        W_out, W_rbf, s_wtf + WTF_WOUT, s_wtf + WTF_WRBF,
        HID * HID, RAD * EDGEF);

    // Wc[l] = W_rbf @ We_tf32[l]  (fp32 out)
    for (int l = 0; l < NLAY; l++) {
        k_gemm<<<dim3(2, 1), 256>>>(s_wtf + WTF_WRBF, s_wtf + WTF_WE(l),
                                    nullptr, s_Wc + (size_t)l * 64 * 256,
                                    nullptr, 64, 256, 256, 0, 2);
    }

    // table + edge sort + misc
    k_table<<<dim3(TABN / 8, NLAY), 256>>>(s_Wc, s_tab);
    k_zero4<<<32, 256>>>((float*)s_cnt, 50016 / 4);
    k_hist<<<(NE + 255) / 256, 256>>>(edges, s_cnt);
    k_scan1<<<NTOPS, 512>>>(s_cnt, s_cnt, s_tops);
    k_scan2<<<1, 128>>>(s_tops);
    k_scan3<<<NTOPS, 512>>>(s_cnt, s_tops);
    k_scat<<<(NE + 255) / 256, 256>>>(edges, s_cnt, s_zc, s_ssit);
    k_zero4<<<8, 256>>>(s_gacc, (NG * HID) / 4);

    for (int l = 0; l < NLAY; l++) {
        if (l > 0) {
            k_gemm<<<gridAB, 256>>>(s_ht, s_wtf + WTF_WM1(l),
                                    s_wtf + WTF_WM2(l), s_A, s_B,
                                    NBLK, EDGEF, HID, 2, 2);
        }
        k_edge_lut<<<(NBLK * 64 + 255) / 256, 256>>>(
            s_ssit, s_cnt, s_tab + (size_t)l * TABN * 256, s_A, s_B, s_agg);
        // h += silu(agg @ Wupd[l]); refresh tf32 mirror
        k_gemm<<<gridUpd, 256>>>(s_agg, s_wtf + WTF_WUPD(l), nullptr,
                                 s_h, s_ht, NBLK, HID, EDGEF, 1, 1);
    }

    // block_repr = l2norm(h @ W_out)
    k_gemm<<<gridUpd, 256>>>(s_ht, s_wtf + WTF_WOUT, nullptr, s_tmp, nullptr,
                             NBLK, HID, HID, 0, 1);
    k_rownorm_scatter<<<(NBLK * 32 + 255) / 256, 256>>>(s_tmp, batch_id,
                                                        out_block, s_gacc);
    k_graphnorm<<<(NG * 32 + 255) / 256, 256>>>(s_gacc, out_graph);
}

// round 13
// speedup vs baseline: 1.2484x; 1.1672x over previous
#include <cuda_runtime.h>
#include <cuda_bf16.h>
#include <cuda_fp16.h>
#include <math.h>

#define NATM 200000
#define NBLK 50000
#define NE   450000
#define NG   64
#define HID  128
#define RAD  64
#define EDGEF 256
#define NLAY 3
#define TABN 8192          // nearest-neighbor table, spacing 1/1024 over [0,8)
#define TABSCALE 1024.0f

// ---- scratch layout (single __device__ buffer, float units) ----
static const size_t OFF_H     = 0;          // float [NBLK*128]
static const size_t OFF_HT    = 6400000;    // half  [NBLK*128] fp16 mirror
static const size_t OFF_ZC    = 9600000;    // float [NBLK*4]
static const size_t OFF_A     = 9800000;    // half  [NBLK*256]
static const size_t OFF_B     = 16200000;   // half  [NBLK*256]
static const size_t OFF_AGG   = 22600000;   // half  [NBLK*256] / fp32 tmp [NBLK*128]
static const size_t OFF_TAB   = 29000000;   // half  [3*8192*256]
static const size_t OFF_WC    = 32145728;   // float [3*64*256]
static const size_t OFF_GACC  = 32194880;   // float [64*128]
static const size_t OFF_START = 32203072;   // int   [NBLK+1]
static const size_t OFF_CNT   = 32253088;   // int   [NBLK]
static const size_t OFF_TOPS  = 32303104;   // int   [128]
static const size_t OFF_SSIT  = 32303232;   // int2  [NE]
static const size_t OFF_WTF   = 33203232;   // u32   [262144] fp16-packed weights
static const size_t SCR_TOTAL = 33465376;

// fp16 pair-packed weight sub-offsets (u32 units, relative to OFF_WTF)
#define WTF_WE(l)   ((size_t)(l) * 32768)
#define WTF_WM1(l)  (98304 + (size_t)(l) * 16384)
#define WTF_WM2(l)  (147456 + (size_t)(l) * 16384)
#define WTF_WUPD(l) (196608 + (size_t)(l) * 16384)
#define WTF_WOUT    (245760)
#define WTF_WRBF    (253952)

__device__ __align__(16) float g_scratch[SCR_TOTAL];

#define NTOPS 98   // ceil(NBLK/512)

__device__ __forceinline__ float silu_f(float x) {
    return x / (1.0f + __expf(-x));
}

__device__ __forceinline__ void mma_f16(float* c, const unsigned* a,
                                        const unsigned* b) {
    asm volatile(
        "mma.sync.aligned.m16n8k16.row.col.f32.f16.f16.f32 "
        "{%0,%1,%2,%3}, {%4,%5,%6,%7}, {%8,%9}, {%0,%1,%2,%3};"
        : "+f"(c[0]), "+f"(c[1]), "+f"(c[2]), "+f"(c[3])
        : "r"(a[0]), "r"(a[1]), "r"(a[2]), "r"(a[3]), "r"(b[0]), "r"(b[1]));
}

__device__ __forceinline__ void red4(float* p, float4 v) {
    asm volatile("red.global.add.v4.f32 [%0], {%1,%2,%3,%4};"
                 :: "l"(p), "f"(v.x), "f"(v.y), "f"(v.z), "f"(v.w)
                 : "memory");
}

__device__ __forceinline__ unsigned pack_h2(float a, float b) {
    __half2 h = __floats2half2_rn(a, b);
    return *(unsigned*)&h;
}

// ---------------------------------------------------------------------------
__global__ void k_zero4(float* __restrict__ p, int n4) {
    float4 z = make_float4(0.f, 0.f, 0.f, 0.f);
    for (int i = blockIdx.x * blockDim.x + threadIdx.x; i < n4;
         i += gridDim.x * blockDim.x) {
        ((float4*)p)[i] = z;
    }
}

// pack fp32 weight [K,N] -> fp16 k-pair-interleaved u32 [K/2][N]
__global__ void k_packB(const float* __restrict__ s, unsigned* __restrict__ d,
                        int K2, int N) {
    int idx = blockIdx.x * blockDim.x + threadIdx.x;
    if (idx >= K2 * N) return;
    int i2 = idx / N, n = idx - i2 * N;
    d[idx] = pack_h2(s[(size_t)(2 * i2) * N + n], s[(size_t)(2 * i2 + 1) * N + n]);
}

// pack two weight tensors of identical shape
__global__ void k_packB2(const float* __restrict__ s0,
                         const float* __restrict__ s1,
                         unsigned* __restrict__ d0, unsigned* __restrict__ d1,
                         int K2, int N) {
    int idx = blockIdx.x * blockDim.x + threadIdx.x;
    if (idx >= K2 * N) return;
    int i2 = idx / N, n = idx - i2 * N;
    size_t lo = (size_t)(2 * i2) * N + n, hi = lo + N;
    d0[idx] = pack_h2(s0[lo], s0[hi]);
    d1[idx] = pack_h2(s1[lo], s1[hi]);
}

// fp32 -> flat fp16 (A-operand form)
__global__ void k_packA(const float* __restrict__ s, __half* __restrict__ d,
                        int n) {
    int i = blockIdx.x * blockDim.x + threadIdx.x;
    if (i < n) d[i] = __float2half(s[i]);
}

// ---------------------------------------------------------------------------
// segment boundaries of sorted block_id
// ---------------------------------------------------------------------------
__global__ void k_bounds(const int* __restrict__ bid, int* __restrict__ start) {
    int a = blockIdx.x * blockDim.x + threadIdx.x;
    if (a > NATM) return;
    if (a == 0) {
        int c = bid[0];
        for (int b = 0; b <= c; b++) start[b] = 0;
    } else if (a == NATM) {
        int p = bid[NATM - 1];
        for (int b = p + 1; b <= NBLK; b++) start[b] = NATM;
    } else {
        int p = bid[a - 1], c = bid[a];
        for (int b = p + 1; b <= c; b++) start[b] = a;
    }
}

// ---------------------------------------------------------------------------
// segment-mean pooling: one warp per block; writes h fp32 + fp16 mirror
// ---------------------------------------------------------------------------
__global__ void k_pool(const float* __restrict__ H, const float* __restrict__ Z,
                       const int* __restrict__ start, float* __restrict__ h,
                       unsigned* __restrict__ ht, float* __restrict__ zc,
                       float* __restrict__ outHb) {
    int gt = blockIdx.x * blockDim.x + threadIdx.x;
    int b = gt >> 5;
    int lane = gt & 31;
    if (b >= NBLK) return;
    int lo = start[b], hi = start[b + 1];
    float4 hs = make_float4(0.f, 0.f, 0.f, 0.f);
    for (int a = lo; a < hi; a++) {
        float4 v = *(const float4*)&H[(size_t)a * HID + lane * 4];
        hs.x += v.x; hs.y += v.y; hs.z += v.z; hs.w += v.w;
    }
    float zx = 0.f, zy = 0.f, zz = 0.f;
    for (int a = lo + lane; a < hi; a += 32) {
        zx += Z[a * 3 + 0]; zy += Z[a * 3 + 1]; zz += Z[a * 3 + 2];
    }
#pragma unroll
    for (int o = 16; o > 0; o >>= 1) {
        zx += __shfl_xor_sync(0xffffffffu, zx, o);
        zy += __shfl_xor_sync(0xffffffffu, zy, o);
        zz += __shfl_xor_sync(0xffffffffu, zz, o);
    }
    float cnt = (float)(hi - lo);
    float inv = 1.0f / fmaxf(cnt, 1.0f);
    hs.x *= inv; hs.y *= inv; hs.z *= inv; hs.w *= inv;
    size_t idx = (size_t)b * HID + lane * 4;
    *(float4*)&h[idx] = hs;
    *(float4*)&outHb[idx] = hs;
    uint2 m;
    m.x = pack_h2(hs.x, hs.y);
    m.y = pack_h2(hs.z, hs.w);
    *(uint2*)&ht[(size_t)b * 64 + lane * 2] = m;
    if (lane == 0) {
        zc[b * 4 + 0] = zx * inv;
        zc[b * 4 + 1] = zy * inv;
        zc[b * 4 + 2] = zz * inv;
        zc[b * 4 + 3] = cnt;
    }
}

// ---------------------------------------------------------------------------
// counting sort of edges by dst
// ---------------------------------------------------------------------------
__global__ void k_hist(const int* __restrict__ edges, int* __restrict__ cnt) {
    int e = blockIdx.x * blockDim.x + threadIdx.x;
    if (e < NE) atomicAdd(&cnt[edges[NE + e]], 1);
}

__global__ void k_scan1(const int* __restrict__ cnt, int* __restrict__ offs,
                        int* __restrict__ tops) {
    __shared__ int sh[512];
    int i = blockIdx.x * 512 + threadIdx.x;
    int v = (i < NBLK) ? cnt[i] : 0;
    sh[threadIdx.x] = v;
    __syncthreads();
#pragma unroll
    for (int off = 1; off < 512; off <<= 1) {
        int t = 0;
        if (threadIdx.x >= off) t = sh[threadIdx.x - off];
        __syncthreads();
        if (threadIdx.x >= off) sh[threadIdx.x] += t;
        __syncthreads();
    }
    if (i < NBLK) offs[i] = sh[threadIdx.x] - v;
    if (threadIdx.x == 511) tops[blockIdx.x] = sh[511];
}

__global__ void k_scan2(int* __restrict__ tops) {
    __shared__ int sh[128];
    int v = (threadIdx.x < NTOPS) ? tops[threadIdx.x] : 0;
    sh[threadIdx.x] = v;
    __syncthreads();
#pragma unroll
    for (int off = 1; off < 128; off <<= 1) {
        int t = 0;
        if (threadIdx.x >= off) t = sh[threadIdx.x - off];
        __syncthreads();
        if (threadIdx.x >= off) sh[threadIdx.x] += t;
        __syncthreads();
    }
    if (threadIdx.x < NTOPS) tops[threadIdx.x] = sh[threadIdx.x] - v;
}

__global__ void k_scan3(int* __restrict__ offs, const int* __restrict__ tops) {
    int i = blockIdx.x * 512 + threadIdx.x;
    if (i < NBLK) offs[i] += tops[blockIdx.x];
}

// scatter: sorted position gets (src, nearest table row index)
__global__ void k_scat(const int* __restrict__ edges, int* __restrict__ offs,
                       const float* __restrict__ zc, int2* __restrict__ ssit) {
    int e = blockIdx.x * blockDim.x + threadIdx.x;
    if (e >= NE) return;
    int s = edges[e];
    int d = edges[NE + e];
    int pos = atomicAdd(&offs[d], 1);
    float dx = zc[s * 4 + 0] - zc[d * 4 + 0];
    float dy = zc[s * 4 + 1] - zc[d * 4 + 1];
    float dz = zc[s * 4 + 2] - zc[d * 4 + 2];
    float dd = sqrtf(dx * dx + dy * dy + dz * dz + 1e-12f);
    int it = (int)(dd * TABSCALE + 0.5f);
    if (it > TABN - 1) it = TABN - 1;
    ssit[pos] = make_int2(s, it);
}
// after k_scat, offs[d] holds the END offset of dst-segment d.

// ---------------------------------------------------------------------------
// build fp16 lookup table T[l][g][j] = rbf(g/1024) @ Wc[l]
// ---------------------------------------------------------------------------
__global__ void k_table(const float* __restrict__ Wc, __half* __restrict__ T) {
    __shared__ float rb[8][64];
    int g0 = blockIdx.x * 8, l = blockIdx.y;
    int tid = threadIdx.x;
    for (int i = tid; i < 8 * 64; i += 256) {
        int gi = i >> 6;
        int k = i & 63;
        float dd = (float)(g0 + gi) * (1.0f / TABSCALE)
                 - (6.0f / 63.0f) * (float)k;
        rb[gi][k] = __expf(-10.0f * dd * dd);
    }
    __syncthreads();
    const float* W = Wc + (size_t)l * 64 * 256;
    float acc[8];
#pragma unroll
    for (int gi = 0; gi < 8; gi++) acc[gi] = 0.f;
#pragma unroll 8
    for (int k = 0; k < 64; k++) {
        float w = W[k * 256 + tid];
#pragma unroll
        for (int gi = 0; gi < 8; gi++) acc[gi] += rb[gi][k] * w;
    }
    __half* out = T + ((size_t)l * TABN + g0) * 256 + tid;
#pragma unroll
    for (int gi = 0; gi < 8; gi++) out[gi * 256] = __float2half(acc[gi]);
}

// ---------------------------------------------------------------------------
// fp16 tensor GEMM (m16n8k16): C[M,N] = A[M,K] @ B[K,N]
// A: flat fp16 rows viewed as u32 pairs [M][K2] (K2 = K/2)
// B: fp16 k-pair-interleaved [K2][N] u32
// BM=128 BN=128 BKpairs=16, 256 threads, warps 2x4, warp tile 64x32.
// epi==0: fp32 store. epi==2: fp16 store. epi==1: C0(fp32) += silu(acc),
//         C1 = fp16 mirror. block.x >= ntiles0 -> (B1, C1-output) for epi 0/2.
// ---------------------------------------------------------------------------
__global__ void __launch_bounds__(256)
k_gemm(const unsigned* __restrict__ A, const unsigned* __restrict__ B0,
       const unsigned* __restrict__ B1, void* C0v, void* C1v,
       int M, int N, int K2, int epi, int ntiles0) {
    __shared__ unsigned As[128 * 20];
    __shared__ unsigned Bs[16 * 136];
    int tid = threadIdx.x;
    int warp = tid >> 5, lane = tid & 31;
    int gid = lane >> 2, tig = lane & 3;
    int wm = (warp & 1) * 64, wn = (warp >> 1) * 32;
    int rowBase = blockIdx.y * 128;
    int bx = blockIdx.x;
    const unsigned* B = B0;
    int outSel = 0;
    if (bx >= ntiles0) { B = B1; outSel = 1; bx -= ntiles0; }
    int colBase = bx * 128;

    int a_r = tid >> 2, a_q = (tid & 3) * 4;   // 64 rows x 4 quads, x2 sets
    int b_r = tid >> 5, b_c = (tid & 31) * 4;  // 8 rows x 32 quads, x2 sets

    uint4 av[2], bv[2];
#pragma unroll
    for (int i = 0; i < 2; i++) {
        int r = rowBase + a_r + i * 64;
        av[i] = (r < M) ? *(const uint4*)&A[(size_t)r * K2 + a_q]
                        : make_uint4(0, 0, 0, 0);
    }
#pragma unroll
    for (int i = 0; i < 2; i++)
        bv[i] = *(const uint4*)&B[(size_t)(b_r + i * 8) * N + colBase + b_c];

    float acc[4][4][4];
#pragma unroll
    for (int mt = 0; mt < 4; mt++)
#pragma unroll
        for (int nn = 0; nn < 4; nn++)
#pragma unroll
            for (int q = 0; q < 4; q++) acc[mt][nn][q] = 0.f;

    for (int k0 = 0; k0 < K2; k0 += 16) {
#pragma unroll
        for (int i = 0; i < 2; i++)
            *(uint4*)&As[(a_r + i * 64) * 20 + a_q] = av[i];
#pragma unroll
        for (int i = 0; i < 2; i++)
            *(uint4*)&Bs[(b_r + i * 8) * 136 + b_c] = bv[i];
        __syncthreads();
        if (k0 + 16 < K2) {
#pragma unroll
            for (int i = 0; i < 2; i++) {
                int r = rowBase + a_r + i * 64;
                av[i] = (r < M)
                    ? *(const uint4*)&A[(size_t)r * K2 + k0 + 16 + a_q]
                    : make_uint4(0, 0, 0, 0);
            }
#pragma unroll
            for (int i = 0; i < 2; i++)
                bv[i] = *(const uint4*)
                    &B[(size_t)(k0 + 16 + b_r + i * 8) * N + colBase + b_c];
        }
#pragma unroll
        for (int kk = 0; kk < 2; kk++) {
            unsigned a[4][4], b[4][2];
#pragma unroll
            for (int mt = 0; mt < 4; mt++) {
                int r = wm + mt * 16 + gid;
                a[mt][0] = As[r * 20 + kk * 8 + tig];
                a[mt][1] = As[(r + 8) * 20 + kk * 8 + tig];
                a[mt][2] = As[r * 20 + kk * 8 + tig + 4];
                a[mt][3] = As[(r + 8) * 20 + kk * 8 + tig + 4];
            }
#pragma unroll
            for (int nn = 0; nn < 4; nn++) {
                b[nn][0] = Bs[(kk * 8 + tig) * 136 + wn + nn * 8 + gid];
                b[nn][1] = Bs[(kk * 8 + tig + 4) * 136 + wn + nn * 8 + gid];
            }
#pragma unroll
            for (int mt = 0; mt < 4; mt++)
#pragma unroll
                for (int nn = 0; nn < 4; nn++)
                    mma_f16(acc[mt][nn], a[mt], b[nn]);
        }
        __syncthreads();
    }

#pragma unroll
    for (int mt = 0; mt < 4; mt++) {
#pragma unroll
        for (int nn = 0; nn < 4; nn++) {
            int c = colBase + wn + nn * 8 + 2 * tig;
#pragma unroll
            for (int half = 0; half < 2; half++) {
                int r = rowBase + wm + mt * 16 + gid + half * 8;
                if (r >= M) continue;
                float v0 = acc[mt][nn][half * 2 + 0];
                float v1 = acc[mt][nn][half * 2 + 1];
                size_t idx = (size_t)r * N + c;
                if (epi == 0) {
                    float* C = outSel ? (float*)C1v : (float*)C0v;
                    C[idx] = v0;
                    C[idx + 1] = v1;
                } else if (epi == 2) {
                    unsigned* C = outSel ? (unsigned*)C1v : (unsigned*)C0v;
                    C[idx >> 1] = pack_h2(v0, v1);
                } else {
                    float* Ch = (float*)C0v;
                    unsigned* Cm = (unsigned*)C1v;
                    float n0 = Ch[idx] + silu_f(v0);
                    float n1 = Ch[idx + 1] + silu_f(v1);
                    Ch[idx] = n0; Ch[idx + 1] = n1;
                    Cm[idx >> 1] = pack_h2(n0, n1);
                }
            }
        }
    }
}

// ---------------------------------------------------------------------------
// edge+aggregate kernel: TWO warps per dst block (128 cols each).
// agg[d] = sum_{e in seg(d)} silu(A[src_e] + B[d] + T[row_e])
// A,B,T fp16; agg stored fp16 (A-operand form for upd GEMM).
// ---------------------------------------------------------------------------
__global__ void __launch_bounds__(256)
k_edge_lut(const int2* __restrict__ ssit, const int* __restrict__ eend,
           const __half* __restrict__ Tl, const __half* __restrict__ Ag,
           const __half* __restrict__ Bg, unsigned* __restrict__ agg) {
    int gw = (blockIdx.x * blockDim.x + threadIdx.x) >> 5;
    int d = gw >> 1;
    int hh = gw & 1;
    int lane = threadIdx.x & 31;
    if (d >= NBLK) return;
    int lo = (d > 0) ? eend[d - 1] : 0;
    int hi = eend[d];
    int c = hh * 128 + lane * 4;

    float4 acc = make_float4(0.f, 0.f, 0.f, 0.f);

    if (lo < hi) {
        uint2 braw = *(const uint2*)&Bg[(size_t)d * 256 + c];
        float2 b0 = __half22float2(*(__half2*)&braw.x);
        float2 b1 = __half22float2(*(__half2*)&braw.y);
        for (int e = lo; e < hi; e++) {
            int2 se = ssit[e];
            uint2 araw = *(const uint2*)&Ag[((size_t)se.x << 8) + c];
            uint2 traw = *(const uint2*)&Tl[((size_t)se.y << 8) + c];
            float2 a0 = __half22float2(*(__half2*)&araw.x);
            float2 a1 = __half22float2(*(__half2*)&araw.y);
            float2 t0 = __half22float2(*(__half2*)&traw.x);
            float2 t1 = __half22float2(*(__half2*)&traw.y);
            acc.x += silu_f(a0.x + b0.x + t0.x);
            acc.y += silu_f(a0.y + b0.y + t0.y);
            acc.z += silu_f(a1.x + b1.x + t1.x);
            acc.w += silu_f(a1.y + b1.y + t1.y);
        }
    }
    uint2 o;
    o.x = pack_h2(acc.x, acc.y);
    o.y = pack_h2(acc.z, acc.w);
    *(uint2*)&agg[(size_t)d * 128 + (c >> 1)] = o;
}

// ---------------------------------------------------------------------------
__global__ void k_rownorm_scatter(const float* __restrict__ tmp,
                                  const int* __restrict__ batch_id,
                                  float* __restrict__ out_block,
                                  float* __restrict__ gacc) {
    int gt = blockIdx.x * blockDim.x + threadIdx.x;
    int r = gt >> 5;
    int lane = gt & 31;
    if (r >= NBLK) return;
    float4 v = *(const float4*)&tmp[(size_t)r * HID + lane * 4];
    float ss = v.x * v.x + v.y * v.y + v.z * v.z + v.w * v.w;
#pragma unroll
    for (int o = 16; o > 0; o >>= 1) ss += __shfl_xor_sync(0xffffffffu, ss, o);
    float inv = 1.0f / fmaxf(sqrtf(ss), 1e-12f);
    int g = batch_id[r];
    float4 nv = make_float4(v.x * inv, v.y * inv, v.z * inv, v.w * inv);
    *(float4*)&out_block[(size_t)r * HID + lane * 4] = nv;
    red4(&gacc[g * HID + lane * 4], nv);
}

__global__ void k_graphnorm(const float* __restrict__ gacc,
                            float* __restrict__ out_graph) {
    int gt = blockIdx.x * blockDim.x + threadIdx.x;
    int r = gt >> 5;
    int lane = gt & 31;
    if (r >= NG) return;
    float4 v = *(const float4*)&gacc[r * HID + lane * 4];
    float ss = v.x * v.x + v.y * v.y + v.z * v.z + v.w * v.w;
#pragma unroll
    for (int o = 16; o > 0; o >>= 1) ss += __shfl_xor_sync(0xffffffffu, ss, o);
    float inv = 1.0f / fmaxf(sqrtf(ss), 1e-12f);
    float4 nv = make_float4(v.x * inv, v.y * inv, v.z * inv, v.w * inv);
    *(float4*)&out_graph[r * HID + lane * 4] = nv;
}

// ---------------------------------------------------------------------------
extern "C" void kernel_launch(void* const* d_in, const int* in_sizes, int n_in,
                              void* d_out, int out_size) {
    const float* H      = (const float*)d_in[0];
    const float* Z      = (const float*)d_in[1];
    const float* W_rbf  = (const float*)d_in[2];
    const float* Wm1    = (const float*)d_in[3];
    const float* Wm2    = (const float*)d_in[4];
    const float* We     = (const float*)d_in[5];
    const float* Wupd   = (const float*)d_in[6];
    const float* W_out  = (const float*)d_in[7];
    const int*   block_id = (const int*)d_in[8];
    const int*   batch_id = (const int*)d_in[9];
    const int*   edges    = (const int*)d_in[10];

    float* out = (float*)d_out;
    float* out_Hb    = out;
    float* out_block = out + (size_t)NBLK * HID;
    float* out_graph = out + 2 * (size_t)NBLK * HID;

    void* scrv = nullptr;
    cudaGetSymbolAddress(&scrv, g_scratch);
    float* scr  = (float*)scrv;
    float*    s_h    = scr + OFF_H;
    unsigned* s_ht   = (unsigned*)(scr + OFF_HT);
    float*    s_zc   = scr + OFF_ZC;
    __half*   s_A    = (__half*)(scr + OFF_A);
    __half*   s_B    = (__half*)(scr + OFF_B);
    unsigned* s_agg  = (unsigned*)(scr + OFF_AGG);
    float*    s_tmp  = (float*)(scr + OFF_AGG);   // reused after last layer
    __half*   s_tab  = (__half*)(scr + OFF_TAB);
    float*    s_Wc   = scr + OFF_WC;
    float*    s_gacc = scr + OFF_GACC;
    int*      s_start = (int*)(scr + OFF_START);
    int*      s_cnt   = (int*)(scr + OFF_CNT);
    int*      s_tops  = (int*)(scr + OFF_TOPS);
    int2*     s_ssit  = (int2*)(scr + OFF_SSIT);
    unsigned* s_wtf   = (unsigned*)(scr + OFF_WTF);

    dim3 gridAB(4, (NBLK + 127) / 128);   // 2 tiles Wm1 + 2 tiles Wm2
    dim3 gridUpd(1, (NBLK + 127) / 128);  // N=128, one tile

    // 0: pack Wm1+Wm2 to fp16 pair-interleaved ([384,256] each, layer-safe)
    k_packB2<<<(192 * 256 + 255) / 256, 256>>>(
        Wm1, Wm2, s_wtf + WTF_WM1(0), s_wtf + WTF_WM2(0), 192, 256);
    // 1: bounds, 2: pool (writes h + fp16 mirror)
    k_bounds<<<(NATM + 256) / 256, 256>>>(block_id, s_start);
    k_pool<<<(NBLK * 32 + 255) / 256, 256>>>(H, Z, s_start, s_h, s_ht, s_zc,
                                             out_Hb);
    // 3: layer-0 A/B GEMM (ncu slot), fp16 outputs; K2=64
    k_gemm<<<gridAB, 256>>>(s_ht, s_wtf + WTF_WM1(0), s_wtf + WTF_WM2(0),
                            s_A, s_B, NBLK, EDGEF, 64, 2, 2);

    // remaining weight packing
    k_packB<<<(384 * 256 + 255) / 256, 256>>>(We, s_wtf + WTF_WE(0), 384, 256);
    k_packB<<<(384 * 128 + 255) / 256, 256>>>(Wupd, s_wtf + WTF_WUPD(0),
                                              384, 128);
    k_packB<<<(64 * 128 + 255) / 256, 256>>>(W_out, s_wtf + WTF_WOUT, 64, 128);
    k_packA<<<(RAD * EDGEF + 255) / 256, 256>>>(
        W_rbf, (__half*)(s_wtf + WTF_WRBF), RAD * EDGEF);

    // Wc[l] = W_rbf @ We[l]  (fp16 mma, fp32 out); M=64, K2=128
    for (int l = 0; l < NLAY; l++) {
        k_gemm<<<dim3(2, 1), 256>>>(s_wtf + WTF_WRBF, s_wtf + WTF_WE(l),
                                    nullptr, s_Wc + (size_t)l * 64 * 256,
                                    nullptr, 64, 256, 128, 0, 2);
    }

    // table + edge sort + misc
    k_table<<<dim3(TABN / 8, NLAY), 256>>>(s_Wc, s_tab);
    k_zero4<<<32, 256>>>((float*)s_cnt, 50016 / 4);
    k_hist<<<(NE + 255) / 256, 256>>>(edges, s_cnt);
    k_scan1<<<NTOPS, 512>>>(s_cnt, s_cnt, s_tops);
    k_scan2<<<1, 128>>>(s_tops);
    k_scan3<<<NTOPS, 512>>>(s_cnt, s_tops);
    k_scat<<<(NE + 255) / 256, 256>>>(edges, s_cnt, s_zc, s_ssit);
    k_zero4<<<8, 256>>>(s_gacc, (NG * HID) / 4);

    for (int l = 0; l < NLAY; l++) {
        if (l > 0) {
            k_gemm<<<gridAB, 256>>>(s_ht, s_wtf + WTF_WM1(l),
                                    s_wtf + WTF_WM2(l), s_A, s_B,
                                    NBLK, EDGEF, 64, 2, 2);
        }
        k_edge_lut<<<(NBLK * 64 + 255) / 256, 256>>>(
            s_ssit, s_cnt, s_tab + (size_t)l * TABN * 256, s_A, s_B, s_agg);
        // h += silu(agg @ Wupd[l]); refresh fp16 mirror; K2=128
        k_gemm<<<gridUpd, 256>>>(s_agg, s_wtf + WTF_WUPD(l), nullptr,
                                 s_h, s_ht, NBLK, HID, 128, 1, 1);
    }

    // block_repr = l2norm(h @ W_out); K2=64
    k_gemm<<<gridUpd, 256>>>(s_ht, s_wtf + WTF_WOUT, nullptr, s_tmp, nullptr,
                             NBLK, HID, 64, 0, 1);
    k_rownorm_scatter<<<(NBLK * 32 + 255) / 256, 256>>>(s_tmp, batch_id,
                                                        out_block, s_gacc);
    k_graphnorm<<<(NG * 32 + 255) / 256, 256>>>(s_gacc, out_graph);
}

// round 14
// speedup vs baseline: 1.2844x; 1.0288x over previous
#include <cuda_runtime.h>
#include <cuda_bf16.h>
#include <cuda_fp16.h>
#include <math.h>

#define NATM 200000
#define NBLK 50000
#define NE   450000
#define NG   64
#define HID  128
#define RAD  64
#define EDGEF 256
#define NLAY 3
#define TABN 8192          // nearest-neighbor table, spacing 1/1024 over [0,8)
#define TABSCALE 1024.0f

// ---- scratch layout (single __device__ buffer, float units) ----
static const size_t OFF_H     = 0;          // float [NBLK*128]
static const size_t OFF_HT    = 6400000;    // half  [NBLK*128] fp16 mirror
static const size_t OFF_ZC    = 9600000;    // float [NBLK*4]
static const size_t OFF_A     = 9800000;    // half  [NBLK*256]
static const size_t OFF_B     = 16200000;   // half  [NBLK*256]
static const size_t OFF_AGG   = 22600000;   // half  [NBLK*256] / fp32 tmp [NBLK*128]
static const size_t OFF_TAB   = 29000000;   // half  [3*8192*256]
static const size_t OFF_WC    = 32145728;   // float [3*64*256]
static const size_t OFF_GACC  = 32194880;   // float [64*128]
static const size_t OFF_START = 32203072;   // int   [NBLK+1]
static const size_t OFF_CNT   = 32253088;   // int   [NBLK]
static const size_t OFF_TOPS  = 32303104;   // int   [128]
static const size_t OFF_SSIT  = 32303232;   // int2  [NE]
static const size_t OFF_WTF   = 33203232;   // u32   [262144] fp16-packed weights
static const size_t SCR_TOTAL = 33465376;

// fp16 pair-packed weight sub-offsets (u32 units, relative to OFF_WTF)
#define WTF_WE(l)   ((size_t)(l) * 32768)
#define WTF_WM1(l)  (98304 + (size_t)(l) * 16384)
#define WTF_WM2(l)  (147456 + (size_t)(l) * 16384)
#define WTF_WUPD(l) (196608 + (size_t)(l) * 16384)
#define WTF_WOUT    (245760)
#define WTF_WRBF    (253952)

__device__ __align__(16) float g_scratch[SCR_TOTAL];

#define NTOPS 98   // ceil(NBLK/512)

__device__ __forceinline__ float silu_f(float x) {
    return x / (1.0f + __expf(-x));
}

__device__ __forceinline__ void mma_f16(float* c, const unsigned* a,
                                        const unsigned* b) {
    asm volatile(
        "mma.sync.aligned.m16n8k16.row.col.f32.f16.f16.f32 "
        "{%0,%1,%2,%3}, {%4,%5,%6,%7}, {%8,%9}, {%0,%1,%2,%3};"
        : "+f"(c[0]), "+f"(c[1]), "+f"(c[2]), "+f"(c[3])
        : "r"(a[0]), "r"(a[1]), "r"(a[2]), "r"(a[3]), "r"(b[0]), "r"(b[1]));
}

__device__ __forceinline__ void red4(float* p, float4 v) {
    asm volatile("red.global.add.v4.f32 [%0], {%1,%2,%3,%4};"
                 :: "l"(p), "f"(v.x), "f"(v.y), "f"(v.z), "f"(v.w)
                 : "memory");
}

__device__ __forceinline__ unsigned pack_h2(float a, float b) {
    __half2 h = __floats2half2_rn(a, b);
    return *(unsigned*)&h;
}

// ---------------------------------------------------------------------------
__global__ void k_zero4(float* __restrict__ p, int n4) {
    float4 z = make_float4(0.f, 0.f, 0.f, 0.f);
    for (int i = blockIdx.x * blockDim.x + threadIdx.x; i < n4;
         i += gridDim.x * blockDim.x) {
        ((float4*)p)[i] = z;
    }
}

// pack fp32 weight [K,N] -> fp16 k-pair-interleaved u32 [K/2][N]
__global__ void k_packB(const float* __restrict__ s, unsigned* __restrict__ d,
                        int K2, int N) {
    int idx = blockIdx.x * blockDim.x + threadIdx.x;
    if (idx >= K2 * N) return;
    int i2 = idx / N, n = idx - i2 * N;
    d[idx] = pack_h2(s[(size_t)(2 * i2) * N + n], s[(size_t)(2 * i2 + 1) * N + n]);
}

// pack two weight tensors of identical shape
__global__ void k_packB2(const float* __restrict__ s0,
                         const float* __restrict__ s1,
                         unsigned* __restrict__ d0, unsigned* __restrict__ d1,
                         int K2, int N) {
    int idx = blockIdx.x * blockDim.x + threadIdx.x;
    if (idx >= K2 * N) return;
    int i2 = idx / N, n = idx - i2 * N;
    size_t lo = (size_t)(2 * i2) * N + n, hi = lo + N;
    d0[idx] = pack_h2(s0[lo], s0[hi]);
    d1[idx] = pack_h2(s1[lo], s1[hi]);
}

// fp32 -> flat fp16 (A-operand form)
__global__ void k_packA(const float* __restrict__ s, __half* __restrict__ d,
                        int n) {
    int i = blockIdx.x * blockDim.x + threadIdx.x;
    if (i < n) d[i] = __float2half(s[i]);
}

// ---------------------------------------------------------------------------
// segment boundaries of sorted block_id
// ---------------------------------------------------------------------------
__global__ void k_bounds(const int* __restrict__ bid, int* __restrict__ start) {
    int a = blockIdx.x * blockDim.x + threadIdx.x;
    if (a > NATM) return;
    if (a == 0) {
        int c = bid[0];
        for (int b = 0; b <= c; b++) start[b] = 0;
    } else if (a == NATM) {
        int p = bid[NATM - 1];
        for (int b = p + 1; b <= NBLK; b++) start[b] = NATM;
    } else {
        int p = bid[a - 1], c = bid[a];
        for (int b = p + 1; b <= c; b++) start[b] = a;
    }
}

// ---------------------------------------------------------------------------
// segment-mean pooling: one warp per block; writes h fp32 + fp16 mirror
// ---------------------------------------------------------------------------
__global__ void k_pool(const float* __restrict__ H, const float* __restrict__ Z,
                       const int* __restrict__ start, float* __restrict__ h,
                       unsigned* __restrict__ ht, float* __restrict__ zc,
                       float* __restrict__ outHb) {
    int gt = blockIdx.x * blockDim.x + threadIdx.x;
    int b = gt >> 5;
    int lane = gt & 31;
    if (b >= NBLK) return;
    int lo = start[b], hi = start[b + 1];
    float4 hs = make_float4(0.f, 0.f, 0.f, 0.f);
    for (int a = lo; a < hi; a++) {
        float4 v = *(const float4*)&H[(size_t)a * HID + lane * 4];
        hs.x += v.x; hs.y += v.y; hs.z += v.z; hs.w += v.w;
    }
    float zx = 0.f, zy = 0.f, zz = 0.f;
    for (int a = lo + lane; a < hi; a += 32) {
        zx += Z[a * 3 + 0]; zy += Z[a * 3 + 1]; zz += Z[a * 3 + 2];
    }
#pragma unroll
    for (int o = 16; o > 0; o >>= 1) {
        zx += __shfl_xor_sync(0xffffffffu, zx, o);
        zy += __shfl_xor_sync(0xffffffffu, zy, o);
        zz += __shfl_xor_sync(0xffffffffu, zz, o);
    }
    float cnt = (float)(hi - lo);
    float inv = 1.0f / fmaxf(cnt, 1.0f);
    hs.x *= inv; hs.y *= inv; hs.z *= inv; hs.w *= inv;
    size_t idx = (size_t)b * HID + lane * 4;
    *(float4*)&h[idx] = hs;
    *(float4*)&outHb[idx] = hs;
    uint2 m;
    m.x = pack_h2(hs.x, hs.y);
    m.y = pack_h2(hs.z, hs.w);
    *(uint2*)&ht[(size_t)b * 64 + lane * 2] = m;
    if (lane == 0) {
        zc[b * 4 + 0] = zx * inv;
        zc[b * 4 + 1] = zy * inv;
        zc[b * 4 + 2] = zz * inv;
        zc[b * 4 + 3] = cnt;
    }
}

// ---------------------------------------------------------------------------
// counting sort of edges by dst
// ---------------------------------------------------------------------------
__global__ void k_hist(const int* __restrict__ edges, int* __restrict__ cnt) {
    int e = blockIdx.x * blockDim.x + threadIdx.x;
    if (e < NE) atomicAdd(&cnt[edges[NE + e]], 1);
}

__global__ void k_scan1(const int* __restrict__ cnt, int* __restrict__ offs,
                        int* __restrict__ tops) {
    __shared__ int sh[512];
    int i = blockIdx.x * 512 + threadIdx.x;
    int v = (i < NBLK) ? cnt[i] : 0;
    sh[threadIdx.x] = v;
    __syncthreads();
#pragma unroll
    for (int off = 1; off < 512; off <<= 1) {
        int t = 0;
        if (threadIdx.x >= off) t = sh[threadIdx.x - off];
        __syncthreads();
        if (threadIdx.x >= off) sh[threadIdx.x] += t;
        __syncthreads();
    }
    if (i < NBLK) offs[i] = sh[threadIdx.x] - v;
    if (threadIdx.x == 511) tops[blockIdx.x] = sh[511];
}

__global__ void k_scan2(int* __restrict__ tops) {
    __shared__ int sh[128];
    int v = (threadIdx.x < NTOPS) ? tops[threadIdx.x] : 0;
    sh[threadIdx.x] = v;
    __syncthreads();
#pragma unroll
    for (int off = 1; off < 128; off <<= 1) {
        int t = 0;
        if (threadIdx.x >= off) t = sh[threadIdx.x - off];
        __syncthreads();
        if (threadIdx.x >= off) sh[threadIdx.x] += t;
        __syncthreads();
    }
    if (threadIdx.x < NTOPS) tops[threadIdx.x] = sh[threadIdx.x] - v;
}

__global__ void k_scan3(int* __restrict__ offs, const int* __restrict__ tops) {
    int i = blockIdx.x * 512 + threadIdx.x;
    if (i < NBLK) offs[i] += tops[blockIdx.x];
}

// scatter: sorted position gets (src, nearest table row index)
__global__ void k_scat(const int* __restrict__ edges, int* __restrict__ offs,
                       const float* __restrict__ zc, int2* __restrict__ ssit) {
    int e = blockIdx.x * blockDim.x + threadIdx.x;
    if (e >= NE) return;
    int s = edges[e];
    int d = edges[NE + e];
    int pos = atomicAdd(&offs[d], 1);
    float dx = zc[s * 4 + 0] - zc[d * 4 + 0];
    float dy = zc[s * 4 + 1] - zc[d * 4 + 1];
    float dz = zc[s * 4 + 2] - zc[d * 4 + 2];
    float dd = sqrtf(dx * dx + dy * dy + dz * dz + 1e-12f);
    int it = (int)(dd * TABSCALE + 0.5f);
    if (it > TABN - 1) it = TABN - 1;
    ssit[pos] = make_int2(s, it);
}
// after k_scat, offs[d] holds the END offset of dst-segment d.

// ---------------------------------------------------------------------------
// build fp16 lookup table T[l][g][j] = rbf(g/1024) @ Wc[l]
// ---------------------------------------------------------------------------
__global__ void k_table(const float* __restrict__ Wc, __half* __restrict__ T) {
    __shared__ float rb[8][64];
    int g0 = blockIdx.x * 8, l = blockIdx.y;
    int tid = threadIdx.x;
    for (int i = tid; i < 8 * 64; i += 256) {
        int gi = i >> 6;
        int k = i & 63;
        float dd = (float)(g0 + gi) * (1.0f / TABSCALE)
                 - (6.0f / 63.0f) * (float)k;
        rb[gi][k] = __expf(-10.0f * dd * dd);
    }
    __syncthreads();
    const float* W = Wc + (size_t)l * 64 * 256;
    float acc[8];
#pragma unroll
    for (int gi = 0; gi < 8; gi++) acc[gi] = 0.f;
#pragma unroll 8
    for (int k = 0; k < 64; k++) {
        float w = W[k * 256 + tid];
#pragma unroll
        for (int gi = 0; gi < 8; gi++) acc[gi] += rb[gi][k] * w;
    }
    __half* out = T + ((size_t)l * TABN + g0) * 256 + tid;
#pragma unroll
    for (int gi = 0; gi < 8; gi++) out[gi * 256] = __float2half(acc[gi]);
}

// ---------------------------------------------------------------------------
// fp16 tensor GEMM (m16n8k16): C[M,N] = A[M,K] @ B[K,N]
// A: flat fp16 rows viewed as u32 pairs [M][K2] (K2 = K/2)
// B: fp16 k-pair-interleaved [K2][N] u32
// BM=128 BN=128 BKpairs=16, 256 threads, warps 2x4, warp tile 64x32.
// epi==0: fp32 store. epi==2: fp16 store. epi==1: C0(fp32) += silu(acc),
//         C1 = fp16 mirror. block.x >= ntiles0 -> (B1, C1-output) for epi 0/2.
// ---------------------------------------------------------------------------
__global__ void __launch_bounds__(256)
k_gemm(const unsigned* __restrict__ A, const unsigned* __restrict__ B0,
       const unsigned* __restrict__ B1, void* C0v, void* C1v,
       int M, int N, int K2, int epi, int ntiles0) {
    __shared__ unsigned As[128 * 20];
    __shared__ unsigned Bs[16 * 136];
    int tid = threadIdx.x;
    int warp = tid >> 5, lane = tid & 31;
    int gid = lane >> 2, tig = lane & 3;
    int wm = (warp & 1) * 64, wn = (warp >> 1) * 32;
    int rowBase = blockIdx.y * 128;
    int bx = blockIdx.x;
    const unsigned* B = B0;
    int outSel = 0;
    if (bx >= ntiles0) { B = B1; outSel = 1; bx -= ntiles0; }
    int colBase = bx * 128;

    int a_r = tid >> 2, a_q = (tid & 3) * 4;   // 64 rows x 4 quads, x2 sets
    int b_r = tid >> 5, b_c = (tid & 31) * 4;  // 8 rows x 32 quads, x2 sets

    uint4 av[2], bv[2];
#pragma unroll
    for (int i = 0; i < 2; i++) {
        int r = rowBase + a_r + i * 64;
        av[i] = (r < M) ? *(const uint4*)&A[(size_t)r * K2 + a_q]
                        : make_uint4(0, 0, 0, 0);
    }
#pragma unroll
    for (int i = 0; i < 2; i++)
        bv[i] = *(const uint4*)&B[(size_t)(b_r + i * 8) * N + colBase + b_c];

    float acc[4][4][4];
#pragma unroll
    for (int mt = 0; mt < 4; mt++)
#pragma unroll
        for (int nn = 0; nn < 4; nn++)
#pragma unroll
            for (int q = 0; q < 4; q++) acc[mt][nn][q] = 0.f;

    for (int k0 = 0; k0 < K2; k0 += 16) {
#pragma unroll
        for (int i = 0; i < 2; i++)
            *(uint4*)&As[(a_r + i * 64) * 20 + a_q] = av[i];
#pragma unroll
        for (int i = 0; i < 2; i++)
            *(uint4*)&Bs[(b_r + i * 8) * 136 + b_c] = bv[i];
        __syncthreads();
        if (k0 + 16 < K2) {
#pragma unroll
            for (int i = 0; i < 2; i++) {
                int r = rowBase + a_r + i * 64;
                av[i] = (r < M)
                    ? *(const uint4*)&A[(size_t)r * K2 + k0 + 16 + a_q]
                    : make_uint4(0, 0, 0, 0);
            }
#pragma unroll
            for (int i = 0; i < 2; i++)
                bv[i] = *(const uint4*)
                    &B[(size_t)(k0 + 16 + b_r + i * 8) * N + colBase + b_c];
        }
#pragma unroll
        for (int kk = 0; kk < 2; kk++) {
            unsigned a[4][4], b[4][2];
#pragma unroll
            for (int mt = 0; mt < 4; mt++) {
                int r = wm + mt * 16 + gid;
                a[mt][0] = As[r * 20 + kk * 8 + tig];
                a[mt][1] = As[(r + 8) * 20 + kk * 8 + tig];
                a[mt][2] = As[r * 20 + kk * 8 + tig + 4];
                a[mt][3] = As[(r + 8) * 20 + kk * 8 + tig + 4];
            }
#pragma unroll
            for (int nn = 0; nn < 4; nn++) {
                b[nn][0] = Bs[(kk * 8 + tig) * 136 + wn + nn * 8 + gid];
                b[nn][1] = Bs[(kk * 8 + tig + 4) * 136 + wn + nn * 8 + gid];
            }
#pragma unroll
            for (int mt = 0; mt < 4; mt++)
#pragma unroll
                for (int nn = 0; nn < 4; nn++)
                    mma_f16(acc[mt][nn], a[mt], b[nn]);
        }
        __syncthreads();
    }

#pragma unroll
    for (int mt = 0; mt < 4; mt++) {
#pragma unroll
        for (int nn = 0; nn < 4; nn++) {
            int c = colBase + wn + nn * 8 + 2 * tig;
#pragma unroll
            for (int half = 0; half < 2; half++) {
                int r = rowBase + wm + mt * 16 + gid + half * 8;
                if (r >= M) continue;
                float v0 = acc[mt][nn][half * 2 + 0];
                float v1 = acc[mt][nn][half * 2 + 1];
                size_t idx = (size_t)r * N + c;
                if (epi == 0) {
                    float* C = outSel ? (float*)C1v : (float*)C0v;
                    C[idx] = v0;
                    C[idx + 1] = v1;
                } else if (epi == 2) {
                    unsigned* C = outSel ? (unsigned*)C1v : (unsigned*)C0v;
                    C[idx >> 1] = pack_h2(v0, v1);
                } else {
                    float* Ch = (float*)C0v;
                    unsigned* Cm = (unsigned*)C1v;
                    float n0 = Ch[idx] + silu_f(v0);
                    float n1 = Ch[idx + 1] + silu_f(v1);
                    Ch[idx] = n0; Ch[idx + 1] = n1;
                    Cm[idx >> 1] = pack_h2(n0, n1);
                }
            }
        }
    }
}

// ---------------------------------------------------------------------------
// edge+aggregate kernel: TWO warps per dst block (128 cols each).
// agg[d] = sum_{e in seg(d)} silu(A[src_e] + B[d] + T[row_e])
// A,B,T fp16; agg stored fp16 (A-operand form for upd GEMM).
// ---------------------------------------------------------------------------
__global__ void __launch_bounds__(256)
k_edge_lut(const int2* __restrict__ ssit, const int* __restrict__ eend,
           const __half* __restrict__ Tl, const __half* __restrict__ Ag,
           const __half* __restrict__ Bg, unsigned* __restrict__ agg) {
    int gw = (blockIdx.x * blockDim.x + threadIdx.x) >> 5;
    int d = gw >> 1;
    int hh = gw & 1;
    int lane = threadIdx.x & 31;
    if (d >= NBLK) return;
    int lo = (d > 0) ? eend[d - 1] : 0;
    int hi = eend[d];
    int c = hh * 128 + lane * 4;

    float4 acc = make_float4(0.f, 0.f, 0.f, 0.f);

    if (lo < hi) {
        uint2 braw = *(const uint2*)&Bg[(size_t)d * 256 + c];
        float2 b0 = __half22float2(*(__half2*)&braw.x);
        float2 b1 = __half22float2(*(__half2*)&braw.y);
        for (int e = lo; e < hi; e++) {
            int2 se = ssit[e];
            uint2 araw = *(const uint2*)&Ag[((size_t)se.x << 8) + c];
            uint2 traw = *(const uint2*)&Tl[((size_t)se.y << 8) + c];
            float2 a0 = __half22float2(*(__half2*)&araw.x);
            float2 a1 = __half22float2(*(__half2*)&araw.y);
            float2 t0 = __half22float2(*(__half2*)&traw.x);
            float2 t1 = __half22float2(*(__half2*)&traw.y);
            acc.x += silu_f(a0.x + b0.x + t0.x);
            acc.y += silu_f(a0.y + b0.y + t0.y);
            acc.z += silu_f(a1.x + b1.x + t1.x);
            acc.w += silu_f(a1.y + b1.y + t1.y);
        }
    }
    uint2 o;
    o.x = pack_h2(acc.x, acc.y);
    o.y = pack_h2(acc.z, acc.w);
    *(uint2*)&agg[(size_t)d * 128 + (c >> 1)] = o;
}

// ---------------------------------------------------------------------------
__global__ void k_rownorm_scatter(const float* __restrict__ tmp,
                                  const int* __restrict__ batch_id,
                                  float* __restrict__ out_block,
                                  float* __restrict__ gacc) {
    int gt = blockIdx.x * blockDim.x + threadIdx.x;
    int r = gt >> 5;
    int lane = gt & 31;
    if (r >= NBLK) return;
    float4 v = *(const float4*)&tmp[(size_t)r * HID + lane * 4];
    float ss = v.x * v.x + v.y * v.y + v.z * v.z + v.w * v.w;
#pragma unroll
    for (int o = 16; o > 0; o >>= 1) ss += __shfl_xor_sync(0xffffffffu, ss, o);
    float inv = 1.0f / fmaxf(sqrtf(ss), 1e-12f);
    int g = batch_id[r];
    float4 nv = make_float4(v.x * inv, v.y * inv, v.z * inv, v.w * inv);
    *(float4*)&out_block[(size_t)r * HID + lane * 4] = nv;
    red4(&gacc[g * HID + lane * 4], nv);
}

__global__ void k_graphnorm(const float* __restrict__ gacc,
                            float* __restrict__ out_graph) {
    int gt = blockIdx.x * blockDim.x + threadIdx.x;
    int r = gt >> 5;
    int lane = gt & 31;
    if (r >= NG) return;
    float4 v = *(const float4*)&gacc[r * HID + lane * 4];
    float ss = v.x * v.x + v.y * v.y + v.z * v.z + v.w * v.w;
#pragma unroll
    for (int o = 16; o > 0; o >>= 1) ss += __shfl_xor_sync(0xffffffffu, ss, o);
    float inv = 1.0f / fmaxf(sqrtf(ss), 1e-12f);
    float4 nv = make_float4(v.x * inv, v.y * inv, v.z * inv, v.w * inv);
    *(float4*)&out_graph[r * HID + lane * 4] = nv;
}

// ---------------------------------------------------------------------------
extern "C" void kernel_launch(void* const* d_in, const int* in_sizes, int n_in,
                              void* d_out, int out_size) {
    const float* H      = (const float*)d_in[0];
    const float* Z      = (const float*)d_in[1];
    const float* W_rbf  = (const float*)d_in[2];
    const float* Wm1    = (const float*)d_in[3];
    const float* Wm2    = (const float*)d_in[4];
    const float* We     = (const float*)d_in[5];
    const float* Wupd   = (const float*)d_in[6];
    const float* W_out  = (const float*)d_in[7];
    const int*   block_id = (const int*)d_in[8];
    const int*   batch_id = (const int*)d_in[9];
    const int*   edges    = (const int*)d_in[10];

    float* out = (float*)d_out;
    float* out_Hb    = out;
    float* out_block = out + (size_t)NBLK * HID;
    float* out_graph = out + 2 * (size_t)NBLK * HID;

    void* scrv = nullptr;
    cudaGetSymbolAddress(&scrv, g_scratch);
    float* scr  = (float*)scrv;
    float*    s_h    = scr + OFF_H;
    unsigned* s_ht   = (unsigned*)(scr + OFF_HT);
    float*    s_zc   = scr + OFF_ZC;
    __half*   s_A    = (__half*)(scr + OFF_A);
    __half*   s_B    = (__half*)(scr + OFF_B);
    unsigned* s_agg  = (unsigned*)(scr + OFF_AGG);
    float*    s_tmp  = (float*)(scr + OFF_AGG);   // reused after last layer
    __half*   s_tab  = (__half*)(scr + OFF_TAB);
    float*    s_Wc   = scr + OFF_WC;
    float*    s_gacc = scr + OFF_GACC;
    int*      s_start = (int*)(scr + OFF_START);
    int*      s_cnt   = (int*)(scr + OFF_CNT);
    int*      s_tops  = (int*)(scr + OFF_TOPS);
    int2*     s_ssit  = (int2*)(scr + OFF_SSIT);
    unsigned* s_wtf   = (unsigned*)(scr + OFF_WTF);

    dim3 gridAB(4, (NBLK + 127) / 128);   // 2 tiles Wm1 + 2 tiles Wm2
    dim3 gridUpd(1, (NBLK + 127) / 128);  // N=128, one tile

    // ---- fork/join multi-stream DAG (capture-safe) ----
    cudaStream_t sA, sB;
    cudaStreamCreateWithFlags(&sA, cudaStreamNonBlocking);
    cudaStreamCreateWithFlags(&sB, cudaStreamNonBlocking);
    cudaEvent_t eRoot, ePack, eTab, ePool, eSort;
    cudaEventCreateWithFlags(&eRoot, cudaEventDisableTiming);
    cudaEventCreateWithFlags(&ePack, cudaEventDisableTiming);
    cudaEventCreateWithFlags(&eTab,  cudaEventDisableTiming);
    cudaEventCreateWithFlags(&ePool, cudaEventDisableTiming);
    cudaEventCreateWithFlags(&eSort, cudaEventDisableTiming);

    cudaEventRecord(eRoot, 0);
    cudaStreamWaitEvent(sA, eRoot, 0);
    cudaStreamWaitEvent(sB, eRoot, 0);

    // -- stream A: weight packs -> Wc GEMMs -> table --
    k_packB2<<<(192 * 256 + 255) / 256, 256, 0, sA>>>(
        Wm1, Wm2, s_wtf + WTF_WM1(0), s_wtf + WTF_WM2(0), 192, 256);
    cudaEventRecord(ePack, sA);
    k_packB<<<(384 * 256 + 255) / 256, 256, 0, sA>>>(
        We, s_wtf + WTF_WE(0), 384, 256);
    k_packB<<<(384 * 128 + 255) / 256, 256, 0, sA>>>(
        Wupd, s_wtf + WTF_WUPD(0), 384, 128);
    k_packB<<<(64 * 128 + 255) / 256, 256, 0, sA>>>(
        W_out, s_wtf + WTF_WOUT, 64, 128);
    k_packA<<<(RAD * EDGEF + 255) / 256, 256, 0, sA>>>(
        W_rbf, (__half*)(s_wtf + WTF_WRBF), RAD * EDGEF);
    for (int l = 0; l < NLAY; l++) {
        k_gemm<<<dim3(2, 1), 256, 0, sA>>>(
            s_wtf + WTF_WRBF, s_wtf + WTF_WE(l), nullptr,
            s_Wc + (size_t)l * 64 * 256, nullptr, 64, 256, 128, 0, 2);
    }
    k_table<<<dim3(TABN / 8, NLAY), 256, 0, sA>>>(s_Wc, s_tab);
    cudaEventRecord(eTab, sA);

    // -- stream B: sort pre-chain (independent of pool until scat) --
    k_zero4<<<32, 256, 0, sB>>>((float*)s_cnt, 50016 / 4);
    k_hist<<<(NE + 255) / 256, 256, 0, sB>>>(edges, s_cnt);
    k_scan1<<<NTOPS, 512, 0, sB>>>(s_cnt, s_cnt, s_tops);
    k_scan2<<<1, 128, 0, sB>>>(s_tops);
    k_scan3<<<NTOPS, 512, 0, sB>>>(s_cnt, s_tops);

    // -- main stream: bounds -> pool -> AB GEMM l0 --
    k_bounds<<<(NATM + 256) / 256, 256>>>(block_id, s_start);
    k_pool<<<(NBLK * 32 + 255) / 256, 256>>>(H, Z, s_start, s_h, s_ht, s_zc,
                                             out_Hb);
    cudaEventRecord(ePool, 0);
    cudaStreamWaitEvent(0, ePack, 0);
    k_gemm<<<gridAB, 256>>>(s_ht, s_wtf + WTF_WM1(0), s_wtf + WTF_WM2(0),
                            s_A, s_B, NBLK, EDGEF, 64, 2, 2);

    // -- stream B tail: scat (needs zc), gacc zero --
    cudaStreamWaitEvent(sB, ePool, 0);
    k_scat<<<(NE + 255) / 256, 256, 0, sB>>>(edges, s_cnt, s_zc, s_ssit);
    k_zero4<<<8, 256, 0, sB>>>(s_gacc, (NG * HID) / 4);
    cudaEventRecord(eSort, sB);

    // -- join side chains before first edge kernel --
    cudaStreamWaitEvent(0, eTab, 0);
    cudaStreamWaitEvent(0, eSort, 0);

    for (int l = 0; l < NLAY; l++) {
        if (l > 0) {
            k_gemm<<<gridAB, 256>>>(s_ht, s_wtf + WTF_WM1(l),
                                    s_wtf + WTF_WM2(l), s_A, s_B,
                                    NBLK, EDGEF, 64, 2, 2);
        }
        k_edge_lut<<<(NBLK * 64 + 255) / 256, 256>>>(
            s_ssit, s_cnt, s_tab + (size_t)l * TABN * 256, s_A, s_B, s_agg);
        // h += silu(agg @ Wupd[l]); refresh fp16 mirror; K2=128
        k_gemm<<<gridUpd, 256>>>(s_agg, s_wtf + WTF_WUPD(l), nullptr,
                                 s_h, s_ht, NBLK, HID, 128, 1, 1);
    }

    // block_repr = l2norm(h @ W_out); K2=64
    k_gemm<<<gridUpd, 256>>>(s_ht, s_wtf + WTF_WOUT, nullptr, s_tmp, nullptr,
                             NBLK, HID, 64, 0, 1);
    k_rownorm_scatter<<<(NBLK * 32 + 255) / 256, 256>>>(s_tmp, batch_id,
                                                        out_block, s_gacc);
    k_graphnorm<<<(NG * 32 + 255) / 256, 256>>>(s_gacc, out_graph);

    cudaEventDestroy(eRoot);
    cudaEventDestroy(ePack);
    cudaEventDestroy(eTab);
    cudaEventDestroy(ePool);
    cudaEventDestroy(eSort);
    cudaStreamDestroy(sA);
    cudaStreamDestroy(sB);
}

// round 15
// speedup vs baseline: 1.2881x; 1.0028x over previous
#include <cuda_runtime.h>
#include <cuda_bf16.h>
#include <cuda_fp16.h>
#include <math.h>

#define NATM 200000
#define NBLK 50000
#define NE   450000
#define NG   64
#define HID  128
#define RAD  64
#define EDGEF 256
#define NLAY 3
#define TABN 8192          // nearest-neighbor table, spacing 1/1024 over [0,8)
#define TABSCALE 1024.0f

// ---- scratch layout (single __device__ buffer, float units) ----
static const size_t OFF_H     = 0;          // float [NBLK*128]
static const size_t OFF_HT    = 6400000;    // half  [NBLK*128] fp16 mirror
static const size_t OFF_ZC    = 9600000;    // float [NBLK*4]
static const size_t OFF_A     = 9800000;    // half  [NBLK*256]
static const size_t OFF_B     = 16200000;   // half  [NBLK*256]
static const size_t OFF_AGG   = 22600000;   // half  [NBLK*256] / fp32 tmp [NBLK*128]
static const size_t OFF_TAB   = 29000000;   // half  [3*8192*256]
static const size_t OFF_WC    = 32145728;   // float [3*64*256]
static const size_t OFF_GACC  = 32194880;   // float [64*128]
static const size_t OFF_START = 32203072;   // int   [NBLK+1]
static const size_t OFF_CNT   = 32253088;   // int   [NBLK]
static const size_t OFF_TOPS  = 32303104;   // int   [128]
static const size_t OFF_SSIT  = 32303232;   // int2  [NE]
static const size_t OFF_WTF   = 33203232;   // u32   [262144] fp16-packed weights
static const size_t SCR_TOTAL = 33465376;

// fp16 pair-packed weight sub-offsets (u32 units, relative to OFF_WTF)
#define WTF_WE(l)   ((size_t)(l) * 32768)
#define WTF_WM1(l)  (98304 + (size_t)(l) * 16384)
#define WTF_WM2(l)  (147456 + (size_t)(l) * 16384)
#define WTF_WUPD(l) (196608 + (size_t)(l) * 16384)
#define WTF_WOUT    (245760)
#define WTF_WRBF    (253952)

__device__ __align__(16) float g_scratch[SCR_TOTAL];

#define NTOPS 98   // ceil(NBLK/512)

__device__ __forceinline__ float silu_f(float x) {
    return x / (1.0f + __expf(-x));
}

__device__ __forceinline__ void mma_f16(float* c, const unsigned* a,
                                        const unsigned* b) {
    asm volatile(
        "mma.sync.aligned.m16n8k16.row.col.f32.f16.f16.f32 "
        "{%0,%1,%2,%3}, {%4,%5,%6,%7}, {%8,%9}, {%0,%1,%2,%3};"
        : "+f"(c[0]), "+f"(c[1]), "+f"(c[2]), "+f"(c[3])
        : "r"(a[0]), "r"(a[1]), "r"(a[2]), "r"(a[3]), "r"(b[0]), "r"(b[1]));
}

__device__ __forceinline__ void ldsm_x4(unsigned* r, unsigned saddr) {
    asm volatile(
        "ldmatrix.sync.aligned.m8n8.x4.shared.b16 {%0,%1,%2,%3}, [%4];"
        : "=r"(r[0]), "=r"(r[1]), "=r"(r[2]), "=r"(r[3])
        : "r"(saddr));
}

__device__ __forceinline__ void red4(float* p, float4 v) {
    asm volatile("red.global.add.v4.f32 [%0], {%1,%2,%3,%4};"
                 :: "l"(p), "f"(v.x), "f"(v.y), "f"(v.z), "f"(v.w)
                 : "memory");
}

__device__ __forceinline__ unsigned pack_h2(float a, float b) {
    __half2 h = __floats2half2_rn(a, b);
    return *(unsigned*)&h;
}

// ---------------------------------------------------------------------------
__global__ void k_zero4(float* __restrict__ p, int n4) {
    float4 z = make_float4(0.f, 0.f, 0.f, 0.f);
    for (int i = blockIdx.x * blockDim.x + threadIdx.x; i < n4;
         i += gridDim.x * blockDim.x) {
        ((float4*)p)[i] = z;
    }
}

// pack fp32 weight [K,N] -> fp16 k-pair-interleaved u32 [K/2][N]
__global__ void k_packB(const float* __restrict__ s, unsigned* __restrict__ d,
                        int K2, int N) {
    int idx = blockIdx.x * blockDim.x + threadIdx.x;
    if (idx >= K2 * N) return;
    int i2 = idx / N, n = idx - i2 * N;
    d[idx] = pack_h2(s[(size_t)(2 * i2) * N + n], s[(size_t)(2 * i2 + 1) * N + n]);
}

// pack two weight tensors of identical shape
__global__ void k_packB2(const float* __restrict__ s0,
                         const float* __restrict__ s1,
                         unsigned* __restrict__ d0, unsigned* __restrict__ d1,
                         int K2, int N) {
    int idx = blockIdx.x * blockDim.x + threadIdx.x;
    if (idx >= K2 * N) return;
    int i2 = idx / N, n = idx - i2 * N;
    size_t lo = (size_t)(2 * i2) * N + n, hi = lo + N;
    d0[idx] = pack_h2(s0[lo], s0[hi]);
    d1[idx] = pack_h2(s1[lo], s1[hi]);
}

// fp32 -> flat fp16 (A-operand form)
__global__ void k_packA(const float* __restrict__ s, __half* __restrict__ d,
                        int n) {
    int i = blockIdx.x * blockDim.x + threadIdx.x;
    if (i < n) d[i] = __float2half(s[i]);
}

// ---------------------------------------------------------------------------
// segment boundaries of sorted block_id
// ---------------------------------------------------------------------------
__global__ void k_bounds(const int* __restrict__ bid, int* __restrict__ start) {
    int a = blockIdx.x * blockDim.x + threadIdx.x;
    if (a > NATM) return;
    if (a == 0) {
        int c = bid[0];
        for (int b = 0; b <= c; b++) start[b] = 0;
    } else if (a == NATM) {
        int p = bid[NATM - 1];
        for (int b = p + 1; b <= NBLK; b++) start[b] = NATM;
    } else {
        int p = bid[a - 1], c = bid[a];
        for (int b = p + 1; b <= c; b++) start[b] = a;
    }
}

// ---------------------------------------------------------------------------
// segment-mean pooling: one warp per block; writes h fp32 + fp16 mirror
// ---------------------------------------------------------------------------
__global__ void k_pool(const float* __restrict__ H, const float* __restrict__ Z,
                       const int* __restrict__ start, float* __restrict__ h,
                       unsigned* __restrict__ ht, float* __restrict__ zc,
                       float* __restrict__ outHb) {
    int gt = blockIdx.x * blockDim.x + threadIdx.x;
    int b = gt >> 5;
    int lane = gt & 31;
    if (b >= NBLK) return;
    int lo = start[b], hi = start[b + 1];
    float4 hs = make_float4(0.f, 0.f, 0.f, 0.f);
    for (int a = lo; a < hi; a++) {
        float4 v = *(const float4*)&H[(size_t)a * HID + lane * 4];
        hs.x += v.x; hs.y += v.y; hs.z += v.z; hs.w += v.w;
    }
    float zx = 0.f, zy = 0.f, zz = 0.f;
    for (int a = lo + lane; a < hi; a += 32) {
        zx += Z[a * 3 + 0]; zy += Z[a * 3 + 1]; zz += Z[a * 3 + 2];
    }
#pragma unroll
    for (int o = 16; o > 0; o >>= 1) {
        zx += __shfl_xor_sync(0xffffffffu, zx, o);
        zy += __shfl_xor_sync(0xffffffffu, zy, o);
        zz += __shfl_xor_sync(0xffffffffu, zz, o);
    }
    float cnt = (float)(hi - lo);
    float inv = 1.0f / fmaxf(cnt, 1.0f);
    hs.x *= inv; hs.y *= inv; hs.z *= inv; hs.w *= inv;
    size_t idx = (size_t)b * HID + lane * 4;
    *(float4*)&h[idx] = hs;
    *(float4*)&outHb[idx] = hs;
    uint2 m;
    m.x = pack_h2(hs.x, hs.y);
    m.y = pack_h2(hs.z, hs.w);
    *(uint2*)&ht[(size_t)b * 64 + lane * 2] = m;
    if (lane == 0) {
        zc[b * 4 + 0] = zx * inv;
        zc[b * 4 + 1] = zy * inv;
        zc[b * 4 + 2] = zz * inv;
        zc[b * 4 + 3] = cnt;
    }
}

// ---------------------------------------------------------------------------
// counting sort of edges by dst
// ---------------------------------------------------------------------------
__global__ void k_hist(const int* __restrict__ edges, int* __restrict__ cnt) {
    int e = blockIdx.x * blockDim.x + threadIdx.x;
    if (e < NE) atomicAdd(&cnt[edges[NE + e]], 1);
}

__global__ void k_scan1(const int* __restrict__ cnt, int* __restrict__ offs,
                        int* __restrict__ tops) {
    __shared__ int sh[512];
    int i = blockIdx.x * 512 + threadIdx.x;
    int v = (i < NBLK) ? cnt[i] : 0;
    sh[threadIdx.x] = v;
    __syncthreads();
#pragma unroll
    for (int off = 1; off < 512; off <<= 1) {
        int t = 0;
        if (threadIdx.x >= off) t = sh[threadIdx.x - off];
        __syncthreads();
        if (threadIdx.x >= off) sh[threadIdx.x] += t;
        __syncthreads();
    }
    if (i < NBLK) offs[i] = sh[threadIdx.x] - v;
    if (threadIdx.x == 511) tops[blockIdx.x] = sh[511];
}

__global__ void k_scan2(int* __restrict__ tops) {
    __shared__ int sh[128];
    int v = (threadIdx.x < NTOPS) ? tops[threadIdx.x] : 0;
    sh[threadIdx.x] = v;
    __syncthreads();
#pragma unroll
    for (int off = 1; off < 128; off <<= 1) {
        int t = 0;
        if (threadIdx.x >= off) t = sh[threadIdx.x - off];
        __syncthreads();
        if (threadIdx.x >= off) sh[threadIdx.x] += t;
        __syncthreads();
    }
    if (threadIdx.x < NTOPS) tops[threadIdx.x] = sh[threadIdx.x] - v;
}

__global__ void k_scan3(int* __restrict__ offs, const int* __restrict__ tops) {
    int i = blockIdx.x * 512 + threadIdx.x;
    if (i < NBLK) offs[i] += tops[blockIdx.x];
}

// scatter: sorted position gets (src, nearest table row index)
__global__ void k_scat(const int* __restrict__ edges, int* __restrict__ offs,
                       const float* __restrict__ zc, int2* __restrict__ ssit) {
    int e = blockIdx.x * blockDim.x + threadIdx.x;
    if (e >= NE) return;
    int s = edges[e];
    int d = edges[NE + e];
    int pos = atomicAdd(&offs[d], 1);
    float dx = zc[s * 4 + 0] - zc[d * 4 + 0];
    float dy = zc[s * 4 + 1] - zc[d * 4 + 1];
    float dz = zc[s * 4 + 2] - zc[d * 4 + 2];
    float dd = sqrtf(dx * dx + dy * dy + dz * dz + 1e-12f);
    int it = (int)(dd * TABSCALE + 0.5f);
    if (it > TABN - 1) it = TABN - 1;
    ssit[pos] = make_int2(s, it);
}
// after k_scat, offs[d] holds the END offset of dst-segment d.

// ---------------------------------------------------------------------------
// build fp16 lookup table T[l][g][j] = rbf(g/1024) @ Wc[l]
// ---------------------------------------------------------------------------
__global__ void k_table(const float* __restrict__ Wc, __half* __restrict__ T) {
    __shared__ float rb[8][64];
    int g0 = blockIdx.x * 8, l = blockIdx.y;
    int tid = threadIdx.x;
    for (int i = tid; i < 8 * 64; i += 256) {
        int gi = i >> 6;
        int k = i & 63;
        float dd = (float)(g0 + gi) * (1.0f / TABSCALE)
                 - (6.0f / 63.0f) * (float)k;
        rb[gi][k] = __expf(-10.0f * dd * dd);
    }
    __syncthreads();
    const float* W = Wc + (size_t)l * 64 * 256;
    float acc[8];
#pragma unroll
    for (int gi = 0; gi < 8; gi++) acc[gi] = 0.f;
#pragma unroll 8
    for (int k = 0; k < 64; k++) {
        float w = W[k * 256 + tid];
#pragma unroll
        for (int gi = 0; gi < 8; gi++) acc[gi] += rb[gi][k] * w;
    }
    __half* out = T + ((size_t)l * TABN + g0) * 256 + tid;
#pragma unroll
    for (int gi = 0; gi < 8; gi++) out[gi * 256] = __float2half(acc[gi]);
}

// ---------------------------------------------------------------------------
// fp16 tensor GEMM (m16n8k16): C[M,N] = A[M,K] @ B[K,N]
// A: flat fp16 rows viewed as u32 pairs [M][K2] (K2 = K/2)
// B: fp16 k-pair-interleaved [K2][N] u32
// BM=128 BN=128 BKpairs=16, 256 threads, warps 2x4, warp tile 64x32.
// A fragments via ldmatrix.x4 (conflict-free on stride-20 rows).
// epi==0: fp32 store. epi==2: fp16 store. epi==1: C0(fp32) += silu(acc),
//         C1 = fp16 mirror. block.x >= ntiles0 -> (B1, C1-output) for epi 0/2.
// ---------------------------------------------------------------------------
__global__ void __launch_bounds__(256)
k_gemm(const unsigned* __restrict__ A, const unsigned* __restrict__ B0,
       const unsigned* __restrict__ B1, void* C0v, void* C1v,
       int M, int N, int K2, int epi, int ntiles0) {
    __shared__ unsigned As[128 * 20];
    __shared__ unsigned Bs[16 * 136];
    int tid = threadIdx.x;
    int warp = tid >> 5, lane = tid & 31;
    int gid = lane >> 2, tig = lane & 3;
    int wm = (warp & 1) * 64, wn = (warp >> 1) * 32;
    int rowBase = blockIdx.y * 128;
    int bx = blockIdx.x;
    const unsigned* B = B0;
    int outSel = 0;
    if (bx >= ntiles0) { B = B1; outSel = 1; bx -= ntiles0; }
    int colBase = bx * 128;

    int a_r = tid >> 2, a_q = (tid & 3) * 4;   // 64 rows x 4 quads, x2 sets
    int b_r = tid >> 5, b_c = (tid & 31) * 4;  // 8 rows x 32 quads, x2 sets

    // ldmatrix per-lane address base: lane -> (row-in-16, kq-offset)
    int lr = lane & 7;
    int sel = lane >> 3;                 // 0..3
    int aRowLane = ((sel & 1) << 3) + lr;
    int aKqLane = (sel & 2) ? 4 : 0;
    unsigned aBase = (unsigned)__cvta_generic_to_shared(
        &As[(wm + aRowLane) * 20 + aKqLane]);

    uint4 av[2], bv[2];
#pragma unroll
    for (int i = 0; i < 2; i++) {
        int r = rowBase + a_r + i * 64;
        av[i] = (r < M) ? *(const uint4*)&A[(size_t)r * K2 + a_q]
                        : make_uint4(0, 0, 0, 0);
    }
#pragma unroll
    for (int i = 0; i < 2; i++)
        bv[i] = *(const uint4*)&B[(size_t)(b_r + i * 8) * N + colBase + b_c];

    float acc[4][4][4];
#pragma unroll
    for (int mt = 0; mt < 4; mt++)
#pragma unroll
        for (int nn = 0; nn < 4; nn++)
#pragma unroll
            for (int q = 0; q < 4; q++) acc[mt][nn][q] = 0.f;

    for (int k0 = 0; k0 < K2; k0 += 16) {
#pragma unroll
        for (int i = 0; i < 2; i++)
            *(uint4*)&As[(a_r + i * 64) * 20 + a_q] = av[i];
#pragma unroll
        for (int i = 0; i < 2; i++)
            *(uint4*)&Bs[(b_r + i * 8) * 136 + b_c] = bv[i];
        __syncthreads();
        if (k0 + 16 < K2) {
#pragma unroll
            for (int i = 0; i < 2; i++) {
                int r = rowBase + a_r + i * 64;
                av[i] = (r < M)
                    ? *(const uint4*)&A[(size_t)r * K2 + k0 + 16 + a_q]
                    : make_uint4(0, 0, 0, 0);
            }
#pragma unroll
            for (int i = 0; i < 2; i++)
                bv[i] = *(const uint4*)
                    &B[(size_t)(k0 + 16 + b_r + i * 8) * N + colBase + b_c];
        }
#pragma unroll
        for (int kk = 0; kk < 2; kk++) {
            unsigned a[4][4], b[4][2];
#pragma unroll
            for (int mt = 0; mt < 4; mt++) {
                unsigned addr = aBase + (unsigned)((mt * 16 * 20 + kk * 8) * 4);
                ldsm_x4(a[mt], addr);
            }
#pragma unroll
            for (int nn = 0; nn < 4; nn++) {
                b[nn][0] = Bs[(kk * 8 + tig) * 136 + wn + nn * 8 + gid];
                b[nn][1] = Bs[(kk * 8 + tig + 4) * 136 + wn + nn * 8 + gid];
            }
#pragma unroll
            for (int mt = 0; mt < 4; mt++)
#pragma unroll
                for (int nn = 0; nn < 4; nn++)
                    mma_f16(acc[mt][nn], a[mt], b[nn]);
        }
        __syncthreads();
    }

#pragma unroll
    for (int mt = 0; mt < 4; mt++) {
#pragma unroll
        for (int nn = 0; nn < 4; nn++) {
            int c = colBase + wn + nn * 8 + 2 * tig;
#pragma unroll
            for (int half = 0; half < 2; half++) {
                int r = rowBase + wm + mt * 16 + gid + half * 8;
                if (r >= M) continue;
                float v0 = acc[mt][nn][half * 2 + 0];
                float v1 = acc[mt][nn][half * 2 + 1];
                size_t idx = (size_t)r * N + c;
                if (epi == 0) {
                    float* C = outSel ? (float*)C1v : (float*)C0v;
                    C[idx] = v0;
                    C[idx + 1] = v1;
                } else if (epi == 2) {
                    unsigned* C = outSel ? (unsigned*)C1v : (unsigned*)C0v;
                    C[idx >> 1] = pack_h2(v0, v1);
                } else {
                    float* Ch = (float*)C0v;
                    unsigned* Cm = (unsigned*)C1v;
                    float n0 = Ch[idx] + silu_f(v0);
                    float n1 = Ch[idx + 1] + silu_f(v1);
                    Ch[idx] = n0; Ch[idx + 1] = n1;
                    Cm[idx >> 1] = pack_h2(n0, n1);
                }
            }
        }
    }
}

// ---------------------------------------------------------------------------
// edge+aggregate kernel: TWO warps per dst block (128 cols each).
// agg[d] = sum_{e in seg(d)} silu(A[src_e] + B[d] + T[row_e])
// A,B,T fp16; agg stored fp16 (A-operand form for upd GEMM).
// ---------------------------------------------------------------------------
__global__ void __launch_bounds__(256)
k_edge_lut(const int2* __restrict__ ssit, const int* __restrict__ eend,
           const __half* __restrict__ Tl, const __half* __restrict__ Ag,
           const __half* __restrict__ Bg, unsigned* __restrict__ agg) {
    int gw = (blockIdx.x * blockDim.x + threadIdx.x) >> 5;
    int d = gw >> 1;
    int hh = gw & 1;
    int lane = threadIdx.x & 31;
    if (d >= NBLK) return;
    int lo = (d > 0) ? eend[d - 1] : 0;
    int hi = eend[d];
    int c = hh * 128 + lane * 4;

    float4 acc = make_float4(0.f, 0.f, 0.f, 0.f);

    if (lo < hi) {
        uint2 braw = *(const uint2*)&Bg[(size_t)d * 256 + c];
        float2 b0 = __half22float2(*(__half2*)&braw.x);
        float2 b1 = __half22float2(*(__half2*)&braw.y);
        for (int e = lo; e < hi; e++) {
            int2 se = ssit[e];
            uint2 araw = *(const uint2*)&Ag[((size_t)se.x << 8) + c];
            uint2 traw = *(const uint2*)&Tl[((size_t)se.y << 8) + c];
            float2 a0 = __half22float2(*(__half2*)&araw.x);
            float2 a1 = __half22float2(*(__half2*)&araw.y);
            float2 t0 = __half22float2(*(__half2*)&traw.x);
            float2 t1 = __half22float2(*(__half2*)&traw.y);
            acc.x += silu_f(a0.x + b0.x + t0.x);
            acc.y += silu_f(a0.y + b0.y + t0.y);
            acc.z += silu_f(a1.x + b1.x + t1.x);
            acc.w += silu_f(a1.y + b1.y + t1.y);
        }
    }
    uint2 o;
    o.x = pack_h2(acc.x, acc.y);
    o.y = pack_h2(acc.z, acc.w);
    *(uint2*)&agg[(size_t)d * 128 + (c >> 1)] = o;
}

// ---------------------------------------------------------------------------
__global__ void k_rownorm_scatter(const float* __restrict__ tmp,
                                  const int* __restrict__ batch_id,
                                  float* __restrict__ out_block,
                                  float* __restrict__ gacc) {
    int gt = blockIdx.x * blockDim.x + threadIdx.x;
    int r = gt >> 5;
    int lane = gt & 31;
    if (r >= NBLK) return;
    float4 v = *(const float4*)&tmp[(size_t)r * HID + lane * 4];
    float ss = v.x * v.x + v.y * v.y + v.z * v.z + v.w * v.w;
#pragma unroll
    for (int o = 16; o > 0; o >>= 1) ss += __shfl_xor_sync(0xffffffffu, ss, o);
    float inv = 1.0f / fmaxf(sqrtf(ss), 1e-12f);
    int g = batch_id[r];
    float4 nv = make_float4(v.x * inv, v.y * inv, v.z * inv, v.w * inv);
    *(float4*)&out_block[(size_t)r * HID + lane * 4] = nv;
    red4(&gacc[g * HID + lane * 4], nv);
}

__global__ void k_graphnorm(const float* __restrict__ gacc,
                            float* __restrict__ out_graph) {
    int gt = blockIdx.x * blockDim.x + threadIdx.x;
    int r = gt >> 5;
    int lane = gt & 31;
    if (r >= NG) return;
    float4 v = *(const float4*)&gacc[r * HID + lane * 4];
    float ss = v.x * v.x + v.y * v.y + v.z * v.z + v.w * v.w;
#pragma unroll
    for (int o = 16; o > 0; o >>= 1) ss += __shfl_xor_sync(0xffffffffu, ss, o);
    float inv = 1.0f / fmaxf(sqrtf(ss), 1e-12f);
    float4 nv = make_float4(v.x * inv, v.y * inv, v.z * inv, v.w * inv);
    *(float4*)&out_graph[r * HID + lane * 4] = nv;
}

// ---------------------------------------------------------------------------
extern "C" void kernel_launch(void* const* d_in, const int* in_sizes, int n_in,
                              void* d_out, int out_size) {
    const float* H      = (const float*)d_in[0];
    const float* Z      = (const float*)d_in[1];
    const float* W_rbf  = (const float*)d_in[2];
    const float* Wm1    = (const float*)d_in[3];
    const float* Wm2    = (const float*)d_in[4];
    const float* We     = (const float*)d_in[5];
    const float* Wupd   = (const float*)d_in[6];
    const float* W_out  = (const float*)d_in[7];
    const int*   block_id = (const int*)d_in[8];
    const int*   batch_id = (const int*)d_in[9];
    const int*   edges    = (const int*)d_in[10];

    float* out = (float*)d_out;
    float* out_Hb    = out;
    float* out_block = out + (size_t)NBLK * HID;
    float* out_graph = out + 2 * (size_t)NBLK * HID;

    void* scrv = nullptr;
    cudaGetSymbolAddress(&scrv, g_scratch);
    float* scr  = (float*)scrv;
    float*    s_h    = scr + OFF_H;
    unsigned* s_ht   = (unsigned*)(scr + OFF_HT);
    float*    s_zc   = scr + OFF_ZC;
    __half*   s_A    = (__half*)(scr + OFF_A);
    __half*   s_B    = (__half*)(scr + OFF_B);
    unsigned* s_agg  = (unsigned*)(scr + OFF_AGG);
    float*    s_tmp  = (float*)(scr + OFF_AGG);   // reused after last layer
    __half*   s_tab  = (__half*)(scr + OFF_TAB);
    float*    s_Wc   = scr + OFF_WC;
    float*    s_gacc = scr + OFF_GACC;
    int*      s_start = (int*)(scr + OFF_START);
    int*      s_cnt   = (int*)(scr + OFF_CNT);
    int*      s_tops  = (int*)(scr + OFF_TOPS);
    int2*     s_ssit  = (int2*)(scr + OFF_SSIT);
    unsigned* s_wtf   = (unsigned*)(scr + OFF_WTF);

    dim3 gridAB(4, (NBLK + 127) / 128);   // 2 tiles Wm1 + 2 tiles Wm2
    dim3 gridUpd(1, (NBLK + 127) / 128);  // N=128, one tile

    // ---- fork/join multi-stream DAG (capture-safe) ----
    cudaStream_t sA, sB;
    cudaStreamCreateWithFlags(&sA, cudaStreamNonBlocking);
    cudaStreamCreateWithFlags(&sB, cudaStreamNonBlocking);
    cudaEvent_t eRoot, ePack, eTab, ePool, eSort;
    cudaEventCreateWithFlags(&eRoot, cudaEventDisableTiming);
    cudaEventCreateWithFlags(&ePack, cudaEventDisableTiming);
    cudaEventCreateWithFlags(&eTab,  cudaEventDisableTiming);
    cudaEventCreateWithFlags(&ePool, cudaEventDisableTiming);
    cudaEventCreateWithFlags(&eSort, cudaEventDisableTiming);

    cudaEventRecord(eRoot, 0);
    cudaStreamWaitEvent(sA, eRoot, 0);
    cudaStreamWaitEvent(sB, eRoot, 0);

    // -- stream A: weight packs -> Wc GEMMs -> table --
    k_packB2<<<(192 * 256 + 255) / 256, 256, 0, sA>>>(
        Wm1, Wm2, s_wtf + WTF_WM1(0), s_wtf + WTF_WM2(0), 192, 256);
    cudaEventRecord(ePack, sA);
    k_packB<<<(384 * 256 + 255) / 256, 256, 0, sA>>>(
        We, s_wtf + WTF_WE(0), 384, 256);
    k_packB<<<(384 * 128 + 255) / 256, 256, 0, sA>>>(
        Wupd, s_wtf + WTF_WUPD(0), 384, 128);
    k_packB<<<(64 * 128 + 255) / 256, 256, 0, sA>>>(
        W_out, s_wtf + WTF_WOUT, 64, 128);
    k_packA<<<(RAD * EDGEF + 255) / 256, 256, 0, sA>>>(
        W_rbf, (__half*)(s_wtf + WTF_WRBF), RAD * EDGEF);
    for (int l = 0; l < NLAY; l++) {
        k_gemm<<<dim3(2, 1), 256, 0, sA>>>(
            s_wtf + WTF_WRBF, s_wtf + WTF_WE(l), nullptr,
            s_Wc + (size_t)l * 64 * 256, nullptr, 64, 256, 128, 0, 2);
    }
    k_table<<<dim3(TABN / 8, NLAY), 256, 0, sA>>>(s_Wc, s_tab);
    cudaEventRecord(eTab, sA);

    // -- stream B: sort pre-chain (independent of pool until scat) --
    k_zero4<<<32, 256, 0, sB>>>((float*)s_cnt, 50016 / 4);
    k_hist<<<(NE + 255) / 256, 256, 0, sB>>>(edges, s_cnt);
    k_scan1<<<NTOPS, 512, 0, sB>>>(s_cnt, s_cnt, s_tops);
    k_scan2<<<1, 128, 0, sB>>>(s_tops);
    k_scan3<<<NTOPS, 512, 0, sB>>>(s_cnt, s_tops);

    // -- main stream: bounds -> pool -> AB GEMM l0 --
    k_bounds<<<(NATM + 256) / 256, 256>>>(block_id, s_start);
    k_pool<<<(NBLK * 32 + 255) / 256, 256>>>(H, Z, s_start, s_h, s_ht, s_zc,
                                             out_Hb);
    cudaEventRecord(ePool, 0);
    cudaStreamWaitEvent(0, ePack, 0);
    k_gemm<<<gridAB, 256>>>(s_ht, s_wtf + WTF_WM1(0), s_wtf + WTF_WM2(0),
                            s_A, s_B, NBLK, EDGEF, 64, 2, 2);

    // -- stream B tail: scat (needs zc), gacc zero --
    cudaStreamWaitEvent(sB, ePool, 0);
    k_scat<<<(NE + 255) / 256, 256, 0, sB>>>(edges, s_cnt, s_zc, s_ssit);
    k_zero4<<<8, 256, 0, sB>>>(s_gacc, (NG * HID) / 4);
    cudaEventRecord(eSort, sB);

    // -- join side chains before first edge kernel --
    cudaStreamWaitEvent(0, eTab, 0);
    cudaStreamWaitEvent(0, eSort, 0);

    for (int l = 0; l < NLAY; l++) {
        if (l > 0) {
            k_gemm<<<gridAB, 256>>>(s_ht, s_wtf + WTF_WM1(l),
                                    s_wtf + WTF_WM2(l), s_A, s_B,
                                    NBLK, EDGEF, 64, 2, 2);
        }
        k_edge_lut<<<(NBLK * 64 + 255) / 256, 256>>>(
            s_ssit, s_cnt, s_tab + (size_t)l * TABN * 256, s_A, s_B, s_agg);
        // h += silu(agg @ Wupd[l]); refresh fp16 mirror; K2=128
        k_gemm<<<gridUpd, 256>>>(s_agg, s_wtf + WTF_WUPD(l), nullptr,
                                 s_h, s_ht, NBLK, HID, 128, 1, 1);
    }

    // block_repr = l2norm(h @ W_out); K2=64
    k_gemm<<<gridUpd, 256>>>(s_ht, s_wtf + WTF_WOUT, nullptr, s_tmp, nullptr,
                             NBLK, HID, 64, 0, 1);
    k_rownorm_scatter<<<(NBLK * 32 + 255) / 256, 256>>>(s_tmp, batch_id,
                                                        out_block, s_gacc);
    k_graphnorm<<<(NG * 32 + 255) / 256, 256>>>(s_gacc, out_graph);

    cudaEventDestroy(eRoot);
    cudaEventDestroy(ePack);
    cudaEventDestroy(eTab);
    cudaEventDestroy(ePool);
    cudaEventDestroy(eSort);
    cudaStreamDestroy(sA);
    cudaStreamDestroy(sB);
}